// round 4
// baseline (speedup 1.0000x reference)
#include <cuda_runtime.h>
#include <cuda_bf16.h>
#include <math.h>
#include <stdint.h>

#define B_   128
#define T_   64
#define D_   300
#define KPX  320
#define H_   512
#define G4_  2048

#define TM 64
#define TN 128
#define KC 32
#define PAD 40
#define A_BASE(term,stage) ((uint32_t)(((term)*2+(stage))*5120))
#define B_BASE(term,stage) ((uint32_t)(20480u + ((term)*2+(stage))*10240u))
static constexpr int SMEM_MM = 61440;

__device__ __forceinline__ uint32_t smem_u32(const void* p) {
    uint32_t a;
    asm("{ .reg .u64 t; cvta.to.shared.u64 t, %1; cvt.u32.u64 %0, t; }" : "=r"(a) : "l"(p));
    return a;
}
#define CP_ASYNC16(dst, src) \
    asm volatile("cp.async.cg.shared.global [%0], [%1], 16;" :: "r"(dst), "l"(src))
#define CP_COMMIT() asm volatile("cp.async.commit_group;" ::: "memory")
#define CP_WAIT0()  asm volatile("cp.async.wait_group 0;" ::: "memory")
#define LDSM4(r0, r1, r2, r3, addr) \
    asm volatile("ldmatrix.sync.aligned.m8n8.x4.shared.b16 {%0,%1,%2,%3}, [%4];" \
                 : "=r"(r0), "=r"(r1), "=r"(r2), "=r"(r3) : "r"(addr))
#define MMA16816(c, a, b0, b1) \
    asm volatile("mma.sync.aligned.m16n8k16.row.col.f32.bf16.bf16.f32 " \
                 "{%0,%1,%2,%3}, {%4,%5,%6,%7}, {%8,%9}, {%0,%1,%2,%3};" \
                 : "+f"((c)[0]), "+f"((c)[1]), "+f"((c)[2]), "+f"((c)[3]) \
                 : "r"((a)[0]), "r"((a)[1]), "r"((a)[2]), "r"((a)[3]), \
                   "r"(b0), "r"(b1))

__device__ __forceinline__ float sigf(float x) { return __fdividef(1.f, 1.f + __expf(-x)); }
__device__ __forceinline__ float ftanh(float x) { return 1.f - __fdividef(2.f, __expf(2.f * x) + 1.f); }

// ---------------- scratch layout (float units) ----------------
static constexpr size_t OFF_E   = 0;
static constexpr size_t OFF_XG  = OFF_E   + 2ull * B_ * T_ * KPX;
static constexpr size_t OFF_Y   = OFF_XG  + 4ull * B_ * T_ * G4_;
static constexpr size_t OFF_H   = OFF_Y   + 4ull * B_ * T_ * H_;
static constexpr size_t OFF_C   = OFF_H   + 2ull * 4 * B_ * H_;
static constexpr size_t OFF_WYY = OFF_C   + 4ull * B_ * H_;
static constexpr size_t OFF_HWY = OFF_WYY + 2ull * B_ * T_ * H_;
static constexpr size_t OFF_UPT = OFF_HWY + 2ull * B_ * T_ * H_;
static constexpr size_t OFF_R   = OFF_UPT + 2ull * 2 * B_ * 1024;
static constexpr size_t OFF_RL  = OFF_R   + 2ull * B_ * H_;
static constexpr size_t OFF_BP  = OFF_RL  + 2ull * B_ * H_;
static constexpr size_t OFF_WXS = OFF_BP  + 2ull * G4_;
static constexpr size_t OFF_WHS = OFF_WXS + (2ull * 2 * G4_ * KPX) / 2;
static constexpr size_t OFF_WYS = OFF_WHS + (2ull * 2 * G4_ * H_) / 2;
static constexpr size_t OFF_WHA = OFF_WYS + (2ull * H_ * H_) / 2;
static constexpr size_t OFF_WCS = OFF_WHA + (2ull * H_ * H_) / 2;
static constexpr size_t TOTAL_F = OFF_WCS + (2ull * 2 * H_ * H_) / 2;

__device__ __align__(256) float d_buf[TOTAL_F];

__device__ __forceinline__ void split_store(float v, __nv_bfloat16* hi, __nv_bfloat16* lo) {
    __nv_bfloat16 h = __float2bfloat16_rn(v);
    *hi = h;
    *lo = __float2bfloat16_rn(v - __bfloat162float(h));
}

// ---------------- prep: bf16 hi/lo weight splits, [N][K], permuted gates ----
__global__ void k_prep(const float* __restrict__ W1, const float* __restrict__ W2,
                       const float* __restrict__ Wy, const float* __restrict__ Wh,
                       const float* __restrict__ Wr, const float* __restrict__ Wt,
                       const float* __restrict__ b1, const float* __restrict__ b2) {
    float* buf = d_buf;
    __nv_bfloat16* WxS = (__nv_bfloat16*)(buf + OFF_WXS);
    __nv_bfloat16* WhS = (__nv_bfloat16*)(buf + OFF_WHS);
    __nv_bfloat16* WyS = (__nv_bfloat16*)(buf + OFF_WYS);
    __nv_bfloat16* WhA = (__nv_bfloat16*)(buf + OFF_WHA);
    __nv_bfloat16* WcS = (__nv_bfloat16*)(buf + OFF_WCS);
    float* bP = buf + OFF_BP;

    const size_t R1 = 2ull * G4_ * KPX;
    const size_t R2 = 2ull * G4_ * H_;
    const size_t R3 = (size_t)H_ * H_;
    const size_t R4 = (size_t)H_ * H_;
    const size_t R5 = 2ull * H_ * H_;
    const size_t R6 = 2ull * G4_;
    const size_t TOT = R1 + R2 + R3 + R4 + R5 + R6;
    size_t stride = (size_t)gridDim.x * blockDim.x;
    for (size_t id = (size_t)blockIdx.x * blockDim.x + threadIdx.x; id < TOT; id += stride) {
        size_t i = id;
        if (i < R1) {
            int w = (int)(i / ((size_t)G4_ * KPX));
            size_t rem = i % ((size_t)G4_ * KPX);
            int np = (int)(rem / KPX), k = (int)(rem % KPX);
            int col = (np & 3) * H_ + (np >> 2);
            const float* W = w ? W2 : W1;
            float v = (k < D_) ? W[(size_t)k * G4_ + col] : 0.f;
            size_t o = ((size_t)(w * 2) * G4_ + np) * KPX + k;
            split_store(v, WxS + o, WxS + o + (size_t)G4_ * KPX);
            continue;
        }
        i -= R1;
        if (i < R2) {
            int w = (int)(i / ((size_t)G4_ * H_));
            size_t rem = i % ((size_t)G4_ * H_);
            int np = (int)(rem / H_), k = (int)(rem % H_);
            int col = (np & 3) * H_ + (np >> 2);
            const float* W = w ? W2 : W1;
            float v = W[(size_t)(D_ + k) * G4_ + col];
            size_t o = ((size_t)(w * 2) * G4_ + np) * H_ + k;
            split_store(v, WhS + o, WhS + o + (size_t)G4_ * H_);
            continue;
        }
        i -= R2;
        if (i < R3) {
            int n = (int)(i / H_), k = (int)(i % H_);
            size_t o = (size_t)n * H_ + k;
            split_store(Wy[(size_t)k * H_ + n], WyS + o, WyS + o + (size_t)H_ * H_);
            continue;
        }
        i -= R3;
        if (i < R4) {
            int n = (int)(i / H_), k = (int)(i % H_);
            size_t o = (size_t)n * H_ + k;
            split_store(Wh[(size_t)k * H_ + n], WhA + o, WhA + o + (size_t)H_ * H_);
            continue;
        }
        i -= R4;
        if (i < R5) {
            int n = (int)(i / H_), k = (int)(i % H_);
            float v = (n < H_) ? Wr[(size_t)k * H_ + n] : Wt[(size_t)k * H_ + (n - H_)];
            size_t o = (size_t)n * H_ + k;
            split_store(v, WcS + o, WcS + o + 2ull * H_ * H_);
            continue;
        }
        i -= R5;
        {
            int w = (int)(i / G4_), np = (int)(i % G4_);
            int col = (np & 3) * H_ + (np >> 2);
            bP[i] = (w ? b2 : b1)[col];
        }
    }
}

__global__ void k_gather(float* __restrict__ e, const int* __restrict__ t1,
                         const int* __restrict__ t2, const float* __restrict__ emb) {
    size_t total = 2ull * B_ * T_ * KPX;
    size_t stride = (size_t)gridDim.x * blockDim.x;
    for (size_t i = (size_t)blockIdx.x * blockDim.x + threadIdx.x; i < total; i += stride) {
        int which = (int)(i / ((size_t)B_ * T_ * KPX));
        size_t rem = i % ((size_t)B_ * T_ * KPX);
        int bt = (int)(rem / KPX), k = (int)(rem % KPX);
        int tok = (which ? t2 : t1)[bt];
        e[i] = (k < D_) ? emb[(size_t)tok * D_ + k] : 0.f;
    }
}

__global__ void k_zero(float* __restrict__ p, size_t n) {
    size_t stride = (size_t)gridDim.x * blockDim.x;
    for (size_t i = (size_t)blockIdx.x * blockDim.x + threadIdx.x; i < n; i += stride)
        p[i] = 0.f;
}

// ---------------- bf16 mma.sync GEMM ----------------
struct MZ {
    const float*         A;
    const __nv_bfloat16* Bhi;
    const __nv_bfloat16* Blo;
    float*               C;
    const float*         bias;
    const float*         Xg;
    float*               cst;
    float*               hout;
    float*               Yst;
    const int*           sl;
    int                  kstart;
};
struct MP {
    MZ z[4];
    int Klen, lda, ldb, ldc, mode, t;
};

__device__ __forceinline__ void lstm_cell(const MZ& z, int t, int b, int j, int c0,
                                          float gi, float gj, float gf, float go, int lda) {
    float4 x = *(const float4*)(z.Xg + ((size_t)b * T_ + t) * G4_ + c0);
    gi += x.x; gj += x.y; gf += x.z; go += x.w;
    bool act = t < z.sl[b];
    size_t ci = (size_t)b * H_ + j;
    float yv = 0.f;
    if (act) {
        float cc = z.cst[ci];
        float cn = cc * sigf(gf + 1.f) + sigf(gi) * ftanh(gj);
        float hn = ftanh(cn) * sigf(go);
        z.cst[ci] = cn;
        z.hout[ci] = hn;
        yv = hn;
    } else {
        z.hout[ci] = z.A[(size_t)b * lda + j];
    }
    z.Yst[((size_t)b * T_ + t) * H_ + j] = yv;
}

__global__ void __launch_bounds__(128) mm_gemm(MP p) {
    extern __shared__ __align__(16) char smem_raw[];
    uint32_t sb = smem_u32(smem_raw);
    const MZ z = p.z[blockIdx.z];
    int tid = threadIdx.x, lane = tid & 31, wid = tid >> 5;
    int n0 = blockIdx.x * TN, m0 = blockIdx.y * TM;
    int nch = p.Klen / KC;

    const float*         Ag  = z.A   + (size_t)(m0 + (tid >> 1)) * p.lda + z.kstart + (tid & 1) * 16;
    const __nv_bfloat16* Bhg = z.Bhi + (size_t)(n0 + tid) * p.ldb + z.kstart;
    const __nv_bfloat16* Blg = z.Blo + (size_t)(n0 + tid) * p.ldb + z.kstart;

    uint32_t aSt = (uint32_t)((tid >> 1) * PAD + (tid & 1) * 16) * 2;
    uint32_t bSt = (uint32_t)(tid * PAD) * 2;

    float fA[16];
    float acc[4][4][4];
#pragma unroll
    for (int i = 0; i < 4; i++)
#pragma unroll
        for (int j2 = 0; j2 < 4; j2++)
#pragma unroll
            for (int q = 0; q < 4; q++) acc[i][j2][q] = 0.f;

    uint32_t aLd = (uint32_t)((lane & 15) * PAD + ((lane >> 4) << 3)) * 2;
    uint32_t bLd = (uint32_t)(((lane & 7) + ((lane & 16) >> 1)) * PAD + (lane & 8)) * 2;

    // prologue
    {
#pragma unroll
        for (int q = 0; q < 4; q++) {
            CP_ASYNC16(sb + B_BASE(0, 0) + bSt + q * 16, Bhg + q * 8);
            CP_ASYNC16(sb + B_BASE(1, 0) + bSt + q * 16, Blg + q * 8);
        }
        CP_COMMIT();
        const float4* s4 = (const float4*)Ag;
#pragma unroll
        for (int q = 0; q < 4; q++) {
            float4 v = s4[q];
            fA[4 * q] = v.x; fA[4 * q + 1] = v.y; fA[4 * q + 2] = v.z; fA[4 * q + 3] = v.w;
        }
        ushort hi[16], lo[16];
#pragma unroll
        for (int q = 0; q < 16; q++) {
            __nv_bfloat16 hb = __float2bfloat16_rn(fA[q]);
            __nv_bfloat16 lb = __float2bfloat16_rn(fA[q] - __bfloat162float(hb));
            hi[q] = *(ushort*)&hb; lo[q] = *(ushort*)&lb;
        }
        *(uint4*)(smem_raw + A_BASE(0, 0) + aSt)      = *(uint4*)(hi);
        *(uint4*)(smem_raw + A_BASE(0, 0) + aSt + 16) = *(uint4*)(hi + 8);
        *(uint4*)(smem_raw + A_BASE(1, 0) + aSt)      = *(uint4*)(lo);
        *(uint4*)(smem_raw + A_BASE(1, 0) + aSt + 16) = *(uint4*)(lo + 8);
        CP_WAIT0();
        __syncthreads();
    }

    for (int ch = 0; ch < nch; ch++) {
        int s = ch & 1, ns = s ^ 1;
        bool more = (ch + 1) < nch;
        if (more) {
            const __nv_bfloat16* bh2 = Bhg + (ch + 1) * KC;
            const __nv_bfloat16* bl2 = Blg + (ch + 1) * KC;
#pragma unroll
            for (int q = 0; q < 4; q++) {
                CP_ASYNC16(sb + B_BASE(0, ns) + bSt + q * 16, bh2 + q * 8);
                CP_ASYNC16(sb + B_BASE(1, ns) + bSt + q * 16, bl2 + q * 8);
            }
            CP_COMMIT();
            const float4* s4 = (const float4*)(Ag + (ch + 1) * KC);
#pragma unroll
            for (int q = 0; q < 4; q++) {
                float4 v = s4[q];
                fA[4 * q] = v.x; fA[4 * q + 1] = v.y; fA[4 * q + 2] = v.z; fA[4 * q + 3] = v.w;
            }
        }
#pragma unroll
        for (int h16 = 0; h16 < 2; h16++) {
            uint32_t kb = (uint32_t)h16 * 32;
            uint32_t bh[8], bl[8];
#pragma unroll
            for (int g = 0; g < 2; g++) {
                uint32_t rowb = (uint32_t)((wid * 32 + g * 16) * PAD) * 2;
                LDSM4(bh[g * 4 + 0], bh[g * 4 + 1], bh[g * 4 + 2], bh[g * 4 + 3],
                      sb + B_BASE(0, s) + bLd + rowb + kb);
                LDSM4(bl[g * 4 + 0], bl[g * 4 + 1], bl[g * 4 + 2], bl[g * 4 + 3],
                      sb + B_BASE(1, s) + bLd + rowb + kb);
            }
#pragma unroll
            for (int mt = 0; mt < 4; mt++) {
                uint32_t ah[4], al[4];
                uint32_t rowa = (uint32_t)(mt * 16 * PAD) * 2;
                LDSM4(ah[0], ah[1], ah[2], ah[3], sb + A_BASE(0, s) + aLd + rowa + kb);
                LDSM4(al[0], al[1], al[2], al[3], sb + A_BASE(1, s) + aLd + rowa + kb);
#pragma unroll
                for (int nt = 0; nt < 4; nt++) {
                    int bi = (nt >> 1) * 4 + (nt & 1) * 2;
                    MMA16816(acc[mt][nt], ah, bh[bi], bh[bi + 1]);
                    MMA16816(acc[mt][nt], ah, bl[bi], bl[bi + 1]);
                    MMA16816(acc[mt][nt], al, bh[bi], bh[bi + 1]);
                }
            }
        }
        if (more) {
            ushort hi[16], lo[16];
#pragma unroll
            for (int q = 0; q < 16; q++) {
                __nv_bfloat16 hb = __float2bfloat16_rn(fA[q]);
                __nv_bfloat16 lb = __float2bfloat16_rn(fA[q] - __bfloat162float(hb));
                hi[q] = *(ushort*)&hb; lo[q] = *(ushort*)&lb;
            }
            *(uint4*)(smem_raw + A_BASE(0, ns) + aSt)      = *(uint4*)(hi);
            *(uint4*)(smem_raw + A_BASE(0, ns) + aSt + 16) = *(uint4*)(hi + 8);
            *(uint4*)(smem_raw + A_BASE(1, ns) + aSt)      = *(uint4*)(lo);
            *(uint4*)(smem_raw + A_BASE(1, ns) + aSt + 16) = *(uint4*)(lo + 8);
            CP_WAIT0();
        }
        __syncthreads();
    }

    if (p.mode == 0) {
#pragma unroll
        for (int mt = 0; mt < 4; mt++) {
            int r = m0 + mt * 16 + (lane >> 2);
#pragma unroll
            for (int nt = 0; nt < 4; nt++) {
                int c = n0 + wid * 32 + nt * 8 + (lane & 3) * 2;
                float b0 = 0.f, b1 = 0.f;
                if (z.bias) { b0 = z.bias[c]; b1 = z.bias[c + 1]; }
                *(float2*)(z.C + (size_t)r * p.ldc + c) =
                    make_float2(acc[mt][nt][0] + b0, acc[mt][nt][1] + b1);
                *(float2*)(z.C + (size_t)(r + 8) * p.ldc + c) =
                    make_float2(acc[mt][nt][2] + b0, acc[mt][nt][3] + b1);
            }
        }
    } else {
#pragma unroll
        for (int mt = 0; mt < 4; mt++) {
            int r = m0 + mt * 16 + (lane >> 2);
#pragma unroll
            for (int nt = 0; nt < 4; nt++) {
                float fo0 = __shfl_xor_sync(0xffffffffu, acc[mt][nt][0], 1);
                float fo1 = __shfl_xor_sync(0xffffffffu, acc[mt][nt][1], 1);
                float fo2 = __shfl_xor_sync(0xffffffffu, acc[mt][nt][2], 1);
                float fo3 = __shfl_xor_sync(0xffffffffu, acc[mt][nt][3], 1);
                if (!(lane & 1)) {
                    int c0 = n0 + wid * 32 + nt * 8 + (lane & 3) * 2;
                    int j = c0 >> 2;
                    lstm_cell(z, p.t, r,     j, c0, acc[mt][nt][0], acc[mt][nt][1], fo0, fo1, p.lda);
                    lstm_cell(z, p.t, r + 8, j, c0, acc[mt][nt][2], acc[mt][nt][3], fo2, fo3, p.lda);
                }
            }
        }
    }
}

// ---------------- fused attention step ----------------
__global__ void __launch_bounds__(512) k_att_step(
    int t, const float* __restrict__ WyY, const float* __restrict__ HWy,
    const float* __restrict__ uPt, const float* __restrict__ wv,
    const float* __restrict__ Y, float* __restrict__ rbuf, float* __restrict__ rL,
    const int* __restrict__ s1, const int* __restrict__ s2) {
    int b = blockIdx.x, a = blockIdx.y;
    int tid = threadIdx.x, lane = tid & 31, w = tid >> 5;
    __shared__ float sc[64];
    __shared__ float su[512];
    __shared__ float spt[512];
    __shared__ float swv[512];

    {
        const float* u0 = uPt + ((size_t)(a * 2 + 0) * B_ + b) * 1024;
        const float* u1 = uPt + ((size_t)(a * 2 + 1) * B_ + b) * 1024;
        const float* hb = HWy + (size_t)a * B_ * T_ * H_ + ((size_t)b * T_ + t) * H_;
        su[tid]  = u0[tid] + u1[tid] + hb[tid];
        spt[tid] = u0[H_ + tid] + u1[H_ + tid];
        swv[tid] = wv[tid];
    }
    __syncthreads();

    const float* WyYb = WyY + (size_t)a * B_ * T_ * H_ + (size_t)b * T_ * H_;
#pragma unroll
    for (int q = 0; q < 4; q++) {
        int t2 = (w << 2) + q;
        const float* row = WyYb + (size_t)t2 * H_;
        float s = 0.f;
#pragma unroll 4
        for (int hh = lane; hh < H_; hh += 32)
            s += ftanh(row[hh] + su[hh]) * swv[hh];
        for (int o = 16; o; o >>= 1) s += __shfl_xor_sync(0xffffffffu, s, o);
        if (lane == 0) {
            int sl = a ? s2[b] : s1[b];
            sc[t2] = s + (t2 < sl ? 0.f : -10000.f);
        }
    }
    __syncthreads();

    if (w == 0) {
        float v1 = sc[lane], v2 = sc[lane + 32];
        float m = fmaxf(v1, v2);
        for (int o = 16; o; o >>= 1) m = fmaxf(m, __shfl_xor_sync(0xffffffffu, m, o));
        float e1 = __expf(v1 - m), e2 = __expf(v2 - m);
        float s = e1 + e2;
        for (int o = 16; o; o >>= 1) s += __shfl_xor_sync(0xffffffffu, s, o);
        float inv = __fdividef(1.f, s);
        sc[lane] = e1 * inv;
        sc[lane + 32] = e2 * inv;
    }
    __syncthreads();

    int hh = tid;
    const float* Yb = Y + (size_t)(a ? 2 : 0) * B_ * T_ * H_ + (size_t)b * T_ * H_ + hh;
    float acc = 0.f;
#pragma unroll
    for (int t2 = 0; t2 < T_; t2++) acc += sc[t2] * Yb[(size_t)t2 * H_];
    float rn = acc + ftanh(spt[hh]);
    int sl2 = a ? s1[b] : s2[b];
    if (t == sl2 - 1) rL[((size_t)a * B_ + b) * H_ + hh] = rn;
    rbuf[((size_t)a * B_ + b) * H_ + hh] = rn;
}

// ---------------- final projection ----------------
__global__ void __launch_bounds__(512) k_final(
    const float* __restrict__ rL, const float* __restrict__ hfin,
    const float* __restrict__ Wp, const float* __restrict__ Wx,
    const float* __restrict__ U, const float* __restrict__ bU,
    float* __restrict__ out) {
    int b = blockIdx.x;
    int tid = threadIdx.x;
    __shared__ float s_in[4][512];
    __shared__ float s_sum[512];
    __shared__ float red0[16], red1[16];
    s_in[0][tid] = rL[(size_t)b * H_ + tid];
    s_in[1][tid] = hfin[((size_t)1 * B_ + b) * H_ + tid];
    s_in[2][tid] = rL[((size_t)B_ + b) * H_ + tid];
    s_in[3][tid] = hfin[((size_t)3 * B_ + b) * H_ + tid];
    __syncthreads();
    float acc0 = 0.f, acc1 = 0.f;
    for (int k = 0; k < H_; k++) {
        float wp = Wp[(size_t)k * H_ + tid];
        float wx = Wx[(size_t)k * H_ + tid];
        acc0 += s_in[0][k] * wp + s_in[1][k] * wx;
        acc1 += s_in[2][k] * wp + s_in[3][k] * wx;
    }
    s_sum[tid] = ftanh(acc0) + ftanh(acc1);
    __syncthreads();
    float p0 = s_sum[tid] * U[(size_t)tid * 2 + 0];
    float p1 = s_sum[tid] * U[(size_t)tid * 2 + 1];
    for (int o = 16; o; o >>= 1) {
        p0 += __shfl_xor_sync(0xffffffffu, p0, o);
        p1 += __shfl_xor_sync(0xffffffffu, p1, o);
    }
    int wp_ = tid >> 5;
    if ((tid & 31) == 0) { red0[wp_] = p0; red1[wp_] = p1; }
    __syncthreads();
    if (tid < 16) {
        p0 = red0[tid]; p1 = red1[tid];
        for (int o = 8; o; o >>= 1) {
            p0 += __shfl_xor_sync(0x0000ffffu, p0, o);
            p1 += __shfl_xor_sync(0x0000ffffu, p1, o);
        }
        if (tid == 0) {
            out[b * 2 + 0] = p0 + bU[0];
            out[b * 2 + 1] = p1 + bU[1];
        }
    }
}

// ---------------- host ----------------
extern "C" void kernel_launch(void* const* d_in, const int* in_sizes, int n_in,
                              void* d_out, int out_size) {
    (void)in_sizes; (void)n_in; (void)out_size;
    const int*   tokens1 = (const int*)d_in[0];
    const int*   tokens2 = (const int*)d_in[1];
    const int*   seqlen1 = (const int*)d_in[2];
    const int*   seqlen2 = (const int*)d_in[3];
    const float* emb = (const float*)d_in[4];
    const float* W1  = (const float*)d_in[5];
    const float* b1  = (const float*)d_in[6];
    const float* W2  = (const float*)d_in[7];
    const float* b2  = (const float*)d_in[8];
    const float* Wy  = (const float*)d_in[9];
    const float* Wh  = (const float*)d_in[10];
    const float* Wr  = (const float*)d_in[11];
    const float* wv  = (const float*)d_in[12];
    const float* Wt  = (const float*)d_in[13];
    const float* Wp  = (const float*)d_in[14];
    const float* Wx  = (const float*)d_in[15];
    const float* U   = (const float*)d_in[16];
    const float* bU  = (const float*)d_in[17];
    float* out = (float*)d_out;

    cudaFuncSetAttribute(mm_gemm, cudaFuncAttributeMaxDynamicSharedMemorySize, SMEM_MM);

    float* buf = nullptr;
    cudaGetSymbolAddress((void**)&buf, d_buf);
    float* e    = buf + OFF_E;
    float* Xg   = buf + OFF_XG;
    float* Yb   = buf + OFF_Y;
    float* hBuf = buf + OFF_H;
    float* cS   = buf + OFF_C;
    float* WyY  = buf + OFF_WYY;
    float* HWy  = buf + OFF_HWY;
    float* uPt  = buf + OFF_UPT;
    float* rbuf = buf + OFF_R;
    float* rL   = buf + OFF_RL;
    float* bP   = buf + OFF_BP;
    __nv_bfloat16* WxS = (__nv_bfloat16*)(buf + OFF_WXS);
    __nv_bfloat16* WhS = (__nv_bfloat16*)(buf + OFF_WHS);
    __nv_bfloat16* WyS = (__nv_bfloat16*)(buf + OFF_WYS);
    __nv_bfloat16* WhA = (__nv_bfloat16*)(buf + OFF_WHA);
    __nv_bfloat16* WcS = (__nv_bfloat16*)(buf + OFF_WCS);

    const size_t HBUF = 4ull * B_ * H_;

    k_prep<<<1024, 256>>>(W1, W2, Wy, Wh, Wr, Wt, b1, b2);
    k_gather<<<2048, 256>>>(e, tokens1, tokens2, emb);
    k_zero<<<512, 256>>>(hBuf, 2 * HBUF + 4ull * B_ * H_);
    k_zero<<<128, 256>>>(rbuf, 2ull * B_ * H_);

    const int iidx[4] = {0, 1, 1, 0}, widx[4] = {0, 1, 0, 1};

    // X-part
    {
        MP p = {};
        for (int r = 0; r < 4; r++) {
            p.z[r].A    = e + (size_t)iidx[r] * B_ * T_ * KPX;
            p.z[r].Bhi  = WxS + (size_t)(widx[r] * 2 + 0) * G4_ * KPX;
            p.z[r].Blo  = WxS + (size_t)(widx[r] * 2 + 1) * G4_ * KPX;
            p.z[r].C    = Xg + (size_t)r * B_ * T_ * G4_;
            p.z[r].bias = bP + (size_t)widx[r] * G4_;
        }
        p.Klen = KPX; p.lda = KPX; p.ldb = KPX; p.ldc = G4_; p.mode = 0;
        mm_gemm<<<dim3(G4_ / TN, (B_ * T_) / TM, 4), 128, SMEM_MM>>>(p);
    }

    // LSTM scan
    for (int t = 0; t < T_; t++) {
        float* hin  = hBuf + (size_t)(t & 1) * HBUF;
        float* hout = hBuf + (size_t)((t + 1) & 1) * HBUF;
        MP p = {};
        for (int r = 0; r < 4; r++) {
            p.z[r].A    = hin + (size_t)r * B_ * H_;
            p.z[r].Bhi  = WhS + (size_t)(widx[r] * 2 + 0) * G4_ * H_;
            p.z[r].Blo  = WhS + (size_t)(widx[r] * 2 + 1) * G4_ * H_;
            p.z[r].Xg   = Xg + (size_t)r * B_ * T_ * G4_;
            p.z[r].cst  = cS + (size_t)r * B_ * H_;
            p.z[r].hout = hout + (size_t)r * B_ * H_;
            p.z[r].Yst  = Yb + (size_t)r * B_ * T_ * H_;
            p.z[r].sl   = (r == 0 || r == 3) ? seqlen1 : seqlen2;
        }
        p.Klen = H_; p.lda = H_; p.ldb = H_; p.mode = 1; p.t = t;
        mm_gemm<<<dim3(G4_ / TN, B_ / TM, 4), 128, SMEM_MM>>>(p);
    }

    // WyY (runs 0,2 @ Wy) + HWy (runs 1,3 @ Wh)
    {
        MP p = {};
        const int runs[4] = {0, 2, 1, 3};
        for (int q = 0; q < 4; q++) {
            p.z[q].A   = Yb + (size_t)runs[q] * B_ * T_ * H_;
            p.z[q].Bhi = (q < 2 ? WyS : WhA);
            p.z[q].Blo = (q < 2 ? WyS : WhA) + (size_t)H_ * H_;
            p.z[q].C   = (q < 2 ? WyY + (size_t)q * B_ * T_ * H_
                                : HWy + (size_t)(q - 2) * B_ * T_ * H_);
        }
        p.Klen = H_; p.lda = H_; p.ldb = H_; p.ldc = H_; p.mode = 0;
        mm_gemm<<<dim3(H_ / TN, (B_ * T_) / TM, 4), 128, SMEM_MM>>>(p);
    }

    // Attention scan (split-K x2 per asym)
    for (int t = 0; t < T_; t++) {
        MP p = {};
        for (int zi = 0; zi < 4; zi++) {
            int a = zi >> 1, part = zi & 1;
            p.z[zi].A      = rbuf + (size_t)a * B_ * H_;
            p.z[zi].Bhi    = WcS;
            p.z[zi].Blo    = WcS + 2ull * H_ * H_;
            p.z[zi].C      = uPt + (size_t)zi * B_ * 1024;
            p.z[zi].kstart = part * 256;
        }
        p.Klen = 256; p.lda = H_; p.ldb = H_; p.ldc = 1024; p.mode = 0;
        mm_gemm<<<dim3(1024 / TN, B_ / TM, 4), 128, SMEM_MM>>>(p);
        k_att_step<<<dim3(B_, 2), 512>>>(t, WyY, HWy, uPt, wv, Yb, rbuf, rL,
                                         seqlen1, seqlen2);
    }

    k_final<<<B_, 512>>>(rL, hBuf, Wp, Wx, U, bU, out);
}

// round 5
// speedup vs baseline: 1.2634x; 1.2634x over previous
#include <cuda_runtime.h>
#include <cuda_bf16.h>
#include <math.h>
#include <stdint.h>

#define B_   128
#define T_   64
#define D_   300
#define KPX  320
#define H_   512
#define G4_  2048

#define TM 64
#define TN 128
#define KC 32
#define PAD 40
#define A_BASE(term,stage) ((uint32_t)(((term)*2+(stage))*5120))
#define B_BASE(term,stage) ((uint32_t)(20480u + ((term)*2+(stage))*10240u))
static constexpr int SMEM_MM = 61440;

__device__ __forceinline__ uint32_t smem_u32(const void* p) {
    uint32_t a;
    asm("{ .reg .u64 t; cvta.to.shared.u64 t, %1; cvt.u32.u64 %0, t; }" : "=r"(a) : "l"(p));
    return a;
}
#define CP_ASYNC16(dst, src) \
    asm volatile("cp.async.cg.shared.global [%0], [%1], 16;" :: "r"(dst), "l"(src))
#define CP_COMMIT() asm volatile("cp.async.commit_group;" ::: "memory")
#define CP_WAIT0()  asm volatile("cp.async.wait_group 0;" ::: "memory")
#define LDSM4(r0, r1, r2, r3, addr) \
    asm volatile("ldmatrix.sync.aligned.m8n8.x4.shared.b16 {%0,%1,%2,%3}, [%4];" \
                 : "=r"(r0), "=r"(r1), "=r"(r2), "=r"(r3) : "r"(addr))
#define MMA16816(c, a, b0, b1) \
    asm volatile("mma.sync.aligned.m16n8k16.row.col.f32.bf16.bf16.f32 " \
                 "{%0,%1,%2,%3}, {%4,%5,%6,%7}, {%8,%9}, {%0,%1,%2,%3};" \
                 : "+f"((c)[0]), "+f"((c)[1]), "+f"((c)[2]), "+f"((c)[3]) \
                 : "r"((a)[0]), "r"((a)[1]), "r"((a)[2]), "r"((a)[3]), \
                   "r"(b0), "r"(b1))

__device__ __forceinline__ float sigf(float x) { return __fdividef(1.f, 1.f + __expf(-x)); }
__device__ __forceinline__ float ftanh(float x) { return 1.f - __fdividef(2.f, __expf(2.f * x) + 1.f); }
__device__ __forceinline__ float tanha(float x) {
    float y; asm("tanh.approx.f32 %0, %1;" : "=f"(y) : "f"(x)); return y;
}

// ---------------- scratch layout (float units) ----------------
static constexpr size_t OFF_E    = 0;
static constexpr size_t OFF_XG   = OFF_E   + 2ull * B_ * T_ * KPX;
static constexpr size_t OFF_Y    = OFF_XG  + 4ull * B_ * T_ * G4_;
static constexpr size_t OFF_H    = OFF_Y   + 4ull * B_ * T_ * H_;
static constexpr size_t OFF_C    = OFF_H   + 2ull * 4 * B_ * H_;
static constexpr size_t OFF_WYY  = OFF_C   + 4ull * B_ * H_;
static constexpr size_t OFF_HWY  = OFF_WYY + 2ull * B_ * T_ * H_;
static constexpr size_t OFF_UPT  = OFF_HWY + 2ull * B_ * T_ * H_;       // [4 ks][256 m][1024]
static constexpr size_t OFF_R    = OFF_UPT + 4ull * 256 * 1024;         // [256][512]
static constexpr size_t OFF_RL   = OFF_R   + 256ull * H_;
static constexpr size_t OFF_BP   = OFF_RL  + 256ull * H_;
static constexpr size_t OFF_WXS  = OFF_BP  + 2ull * G4_;
static constexpr size_t OFF_WHS  = OFF_WXS + (2ull * 2 * G4_ * KPX) / 2;
static constexpr size_t OFF_WYS  = OFF_WHS + (2ull * 2 * G4_ * H_) / 2;
static constexpr size_t OFF_WHA  = OFF_WYS + (2ull * H_ * H_) / 2;
static constexpr size_t OFF_WCS  = OFF_WHA + (2ull * H_ * H_) / 2;
static constexpr size_t OFF_SYNC = OFF_WCS + (2ull * 2 * H_ * H_) / 2;  // 16 words
static constexpr size_t TOTAL_F  = OFF_SYNC + 16;

__device__ __align__(256) float d_buf[TOTAL_F];

__device__ __forceinline__ void split_store(float v, __nv_bfloat16* hi, __nv_bfloat16* lo) {
    __nv_bfloat16 h = __float2bfloat16_rn(v);
    *hi = h;
    *lo = __float2bfloat16_rn(v - __bfloat162float(h));
}

// ---------------- global grid barrier (state pre-zeroed by k_zero) --------
__device__ __forceinline__ void gbar(unsigned* cnt, volatile unsigned* rel,
                                     unsigned seq, unsigned ncta) {
    __syncthreads();
    if (threadIdx.x == 0) {
        __threadfence();
        unsigned v = atomicAdd(cnt, 1u) + 1u;
        if (v == ncta * seq) atomicExch((unsigned*)rel, seq);
        while (*rel < seq) { }
        __threadfence();
    }
    __syncthreads();
}

// ---------------- prep ----------------
__global__ void k_prep(const float* __restrict__ W1, const float* __restrict__ W2,
                       const float* __restrict__ Wy, const float* __restrict__ Wh,
                       const float* __restrict__ Wr, const float* __restrict__ Wt,
                       const float* __restrict__ b1, const float* __restrict__ b2) {
    float* buf = d_buf;
    __nv_bfloat16* WxS = (__nv_bfloat16*)(buf + OFF_WXS);
    __nv_bfloat16* WhS = (__nv_bfloat16*)(buf + OFF_WHS);
    __nv_bfloat16* WyS = (__nv_bfloat16*)(buf + OFF_WYS);
    __nv_bfloat16* WhA = (__nv_bfloat16*)(buf + OFF_WHA);
    __nv_bfloat16* WcS = (__nv_bfloat16*)(buf + OFF_WCS);
    float* bP = buf + OFF_BP;

    const size_t R1 = 2ull * G4_ * KPX;
    const size_t R2 = 2ull * G4_ * H_;
    const size_t R3 = (size_t)H_ * H_;
    const size_t R4 = (size_t)H_ * H_;
    const size_t R5 = 2ull * H_ * H_;
    const size_t R6 = 2ull * G4_;
    const size_t TOT = R1 + R2 + R3 + R4 + R5 + R6;
    size_t stride = (size_t)gridDim.x * blockDim.x;
    for (size_t id = (size_t)blockIdx.x * blockDim.x + threadIdx.x; id < TOT; id += stride) {
        size_t i = id;
        if (i < R1) {
            int w = (int)(i / ((size_t)G4_ * KPX));
            size_t rem = i % ((size_t)G4_ * KPX);
            int np = (int)(rem / KPX), k = (int)(rem % KPX);
            int col = (np & 3) * H_ + (np >> 2);
            const float* W = w ? W2 : W1;
            float v = (k < D_) ? W[(size_t)k * G4_ + col] : 0.f;
            size_t o = ((size_t)(w * 2) * G4_ + np) * KPX + k;
            split_store(v, WxS + o, WxS + o + (size_t)G4_ * KPX);
            continue;
        }
        i -= R1;
        if (i < R2) {
            int w = (int)(i / ((size_t)G4_ * H_));
            size_t rem = i % ((size_t)G4_ * H_);
            int np = (int)(rem / H_), k = (int)(rem % H_);
            int col = (np & 3) * H_ + (np >> 2);
            const float* W = w ? W2 : W1;
            float v = W[(size_t)(D_ + k) * G4_ + col];
            size_t o = ((size_t)(w * 2) * G4_ + np) * H_ + k;
            split_store(v, WhS + o, WhS + o + (size_t)G4_ * H_);
            continue;
        }
        i -= R2;
        if (i < R3) {
            int n = (int)(i / H_), k = (int)(i % H_);
            size_t o = (size_t)n * H_ + k;
            split_store(Wy[(size_t)k * H_ + n], WyS + o, WyS + o + (size_t)H_ * H_);
            continue;
        }
        i -= R3;
        if (i < R4) {
            int n = (int)(i / H_), k = (int)(i % H_);
            size_t o = (size_t)n * H_ + k;
            split_store(Wh[(size_t)k * H_ + n], WhA + o, WhA + o + (size_t)H_ * H_);
            continue;
        }
        i -= R4;
        if (i < R5) {
            int n = (int)(i / H_), k = (int)(i % H_);
            float v = (n < H_) ? Wr[(size_t)k * H_ + n] : Wt[(size_t)k * H_ + (n - H_)];
            size_t o = (size_t)n * H_ + k;
            split_store(v, WcS + o, WcS + o + 2ull * H_ * H_);
            continue;
        }
        i -= R5;
        {
            int w = (int)(i / G4_), np = (int)(i % G4_);
            int col = (np & 3) * H_ + (np >> 2);
            bP[i] = (w ? b2 : b1)[col];
        }
    }
}

__global__ void k_gather(float* __restrict__ e, const int* __restrict__ t1,
                         const int* __restrict__ t2, const float* __restrict__ emb) {
    size_t total = 2ull * B_ * T_ * KPX;
    size_t stride = (size_t)gridDim.x * blockDim.x;
    for (size_t i = (size_t)blockIdx.x * blockDim.x + threadIdx.x; i < total; i += stride) {
        int which = (int)(i / ((size_t)B_ * T_ * KPX));
        size_t rem = i % ((size_t)B_ * T_ * KPX);
        int bt = (int)(rem / KPX), k = (int)(rem % KPX);
        int tok = (which ? t2 : t1)[bt];
        e[i] = (k < D_) ? emb[(size_t)tok * D_ + k] : 0.f;
    }
}

__global__ void k_zero(float* __restrict__ p, size_t n) {
    size_t stride = (size_t)gridDim.x * blockDim.x;
    for (size_t i = (size_t)blockIdx.x * blockDim.x + threadIdx.x; i < n; i += stride)
        p[i] = 0.f;
}

// ---------------------------------------------------------------------------
// Core K-loop: acc += A(fp32, ldcg) x B(bf16 hi/lo), 64x128 tile, 128 threads.
// 3-term bf16 split. Caller zeroes acc. Contains __syncthreads (all-thread).
// ---------------------------------------------------------------------------
__device__ __forceinline__ void gemm_k(
    const float* __restrict__ Ag, const __nv_bfloat16* __restrict__ Bhg,
    const __nv_bfloat16* __restrict__ Blg, int nch,
    char* smem_raw, uint32_t sb,
    uint32_t aSt, uint32_t bSt, uint32_t aLd, uint32_t bLd,
    int wid, float acc[4][4][4]) {
    float fA[16];
    // prologue
    {
#pragma unroll
        for (int q = 0; q < 4; q++) {
            CP_ASYNC16(sb + B_BASE(0, 0) + bSt + q * 16, Bhg + q * 8);
            CP_ASYNC16(sb + B_BASE(1, 0) + bSt + q * 16, Blg + q * 8);
        }
        CP_COMMIT();
        const float4* s4 = (const float4*)Ag;
#pragma unroll
        for (int q = 0; q < 4; q++) {
            float4 v = __ldcg(s4 + q);
            fA[4 * q] = v.x; fA[4 * q + 1] = v.y; fA[4 * q + 2] = v.z; fA[4 * q + 3] = v.w;
        }
        ushort hi[16], lo[16];
#pragma unroll
        for (int q = 0; q < 16; q++) {
            __nv_bfloat16 hb = __float2bfloat16_rn(fA[q]);
            __nv_bfloat16 lb = __float2bfloat16_rn(fA[q] - __bfloat162float(hb));
            hi[q] = *(ushort*)&hb; lo[q] = *(ushort*)&lb;
        }
        *(uint4*)(smem_raw + A_BASE(0, 0) + aSt)      = *(uint4*)(hi);
        *(uint4*)(smem_raw + A_BASE(0, 0) + aSt + 16) = *(uint4*)(hi + 8);
        *(uint4*)(smem_raw + A_BASE(1, 0) + aSt)      = *(uint4*)(lo);
        *(uint4*)(smem_raw + A_BASE(1, 0) + aSt + 16) = *(uint4*)(lo + 8);
        CP_WAIT0();
        __syncthreads();
    }
    for (int ch = 0; ch < nch; ch++) {
        int s = ch & 1, ns = s ^ 1;
        bool more = (ch + 1) < nch;
        if (more) {
            const __nv_bfloat16* bh2 = Bhg + (ch + 1) * KC;
            const __nv_bfloat16* bl2 = Blg + (ch + 1) * KC;
#pragma unroll
            for (int q = 0; q < 4; q++) {
                CP_ASYNC16(sb + B_BASE(0, ns) + bSt + q * 16, bh2 + q * 8);
                CP_ASYNC16(sb + B_BASE(1, ns) + bSt + q * 16, bl2 + q * 8);
            }
            CP_COMMIT();
            const float4* s4 = (const float4*)(Ag + (ch + 1) * KC);
#pragma unroll
            for (int q = 0; q < 4; q++) {
                float4 v = __ldcg(s4 + q);
                fA[4 * q] = v.x; fA[4 * q + 1] = v.y; fA[4 * q + 2] = v.z; fA[4 * q + 3] = v.w;
            }
        }
#pragma unroll
        for (int h16 = 0; h16 < 2; h16++) {
            uint32_t kb = (uint32_t)h16 * 32;
            uint32_t bh[8], bl[8];
#pragma unroll
            for (int g = 0; g < 2; g++) {
                uint32_t rowb = (uint32_t)((wid * 32 + g * 16) * PAD) * 2;
                LDSM4(bh[g * 4 + 0], bh[g * 4 + 1], bh[g * 4 + 2], bh[g * 4 + 3],
                      sb + B_BASE(0, s) + bLd + rowb + kb);
                LDSM4(bl[g * 4 + 0], bl[g * 4 + 1], bl[g * 4 + 2], bl[g * 4 + 3],
                      sb + B_BASE(1, s) + bLd + rowb + kb);
            }
#pragma unroll
            for (int mt = 0; mt < 4; mt++) {
                uint32_t ah[4], al[4];
                uint32_t rowa = (uint32_t)(mt * 16 * PAD) * 2;
                LDSM4(ah[0], ah[1], ah[2], ah[3], sb + A_BASE(0, s) + aLd + rowa + kb);
                LDSM4(al[0], al[1], al[2], al[3], sb + A_BASE(1, s) + aLd + rowa + kb);
#pragma unroll
                for (int nt = 0; nt < 4; nt++) {
                    int bi = (nt >> 1) * 4 + (nt & 1) * 2;
                    MMA16816(acc[mt][nt], ah, bh[bi], bh[bi + 1]);
                    MMA16816(acc[mt][nt], ah, bl[bi], bl[bi + 1]);
                    MMA16816(acc[mt][nt], al, bh[bi], bh[bi + 1]);
                }
            }
        }
        if (more) {
            ushort hi[16], lo[16];
#pragma unroll
            for (int q = 0; q < 16; q++) {
                __nv_bfloat16 hb = __float2bfloat16_rn(fA[q]);
                __nv_bfloat16 lb = __float2bfloat16_rn(fA[q] - __bfloat162float(hb));
                hi[q] = *(ushort*)&hb; lo[q] = *(ushort*)&lb;
            }
            *(uint4*)(smem_raw + A_BASE(0, ns) + aSt)      = *(uint4*)(hi);
            *(uint4*)(smem_raw + A_BASE(0, ns) + aSt + 16) = *(uint4*)(hi + 8);
            *(uint4*)(smem_raw + A_BASE(1, ns) + aSt)      = *(uint4*)(lo);
            *(uint4*)(smem_raw + A_BASE(1, ns) + aSt + 16) = *(uint4*)(lo + 8);
            CP_WAIT0();
        }
        __syncthreads();
    }
}

// ---------------- bulk GEMM (mode 0: C = acc + bias) ----------------
struct MZ {
    const float*         A;
    const __nv_bfloat16* Bhi;
    const __nv_bfloat16* Blo;
    float*               C;
    const float*         bias;
};
struct MP {
    MZ z[4];
    int Klen, lda, ldb, ldc;
};

__global__ void __launch_bounds__(128) mm_gemm(MP p) {
    extern __shared__ __align__(16) char smem_raw[];
    uint32_t sb = smem_u32(smem_raw);
    const MZ z = p.z[blockIdx.z];
    int tid = threadIdx.x, lane = tid & 31, wid = tid >> 5;
    int n0 = blockIdx.x * TN, m0 = blockIdx.y * TM;

    const float*         Ag  = z.A   + (size_t)(m0 + (tid >> 1)) * p.lda + (tid & 1) * 16;
    const __nv_bfloat16* Bhg = z.Bhi + (size_t)(n0 + tid) * p.ldb;
    const __nv_bfloat16* Blg = z.Blo + (size_t)(n0 + tid) * p.ldb;
    uint32_t aSt = (uint32_t)((tid >> 1) * PAD + (tid & 1) * 16) * 2;
    uint32_t bSt = (uint32_t)(tid * PAD) * 2;
    uint32_t aLd = (uint32_t)((lane & 15) * PAD + ((lane >> 4) << 3)) * 2;
    uint32_t bLd = (uint32_t)(((lane & 7) + ((lane & 16) >> 1)) * PAD + (lane & 8)) * 2;

    float acc[4][4][4] = {};
    gemm_k(Ag, Bhg, Blg, p.Klen / KC, smem_raw, sb, aSt, bSt, aLd, bLd, wid, acc);

#pragma unroll
    for (int mt = 0; mt < 4; mt++) {
        int r = m0 + mt * 16 + (lane >> 2);
#pragma unroll
        for (int nt = 0; nt < 4; nt++) {
            int c = n0 + wid * 32 + nt * 8 + (lane & 3) * 2;
            float b0 = 0.f, b1 = 0.f;
            if (z.bias) { b0 = z.bias[c]; b1 = z.bias[c + 1]; }
            *(float2*)(z.C + (size_t)r * p.ldc + c) =
                make_float2(acc[mt][nt][0] + b0, acc[mt][nt][1] + b1);
            *(float2*)(z.C + (size_t)(r + 8) * p.ldc + c) =
                make_float2(acc[mt][nt][2] + b0, acc[mt][nt][3] + b1);
        }
    }
}

// ---------------- persistent LSTM scan (one launch, 128 CTAs) ----------------
__global__ void __launch_bounds__(128) k_lstm_persist(
    const int* __restrict__ s1, const int* __restrict__ s2) {
    extern __shared__ __align__(16) char smem_raw[];
    uint32_t sb = smem_u32(smem_raw);
    float* buf = d_buf;
    int tid = threadIdx.x, lane = tid & 31, wid = tid >> 5;
    int blk = blockIdx.x;
    int r  = blk >> 5;
    int mt_ = (blk >> 4) & 1;
    int nt_ = blk & 15;
    int n0 = nt_ * TN, m0 = mt_ * TM;
    int widx = (r == 0 || r == 2) ? 0 : 1;
    const int* sl = (r == 0 || r == 3) ? s1 : s2;

    const __nv_bfloat16* WhS = (const __nv_bfloat16*)(buf + OFF_WHS);
    const __nv_bfloat16* Bhi = WhS + (size_t)(widx * 2 + 0) * G4_ * H_;
    const __nv_bfloat16* Blo = WhS + (size_t)(widx * 2 + 1) * G4_ * H_;
    const __nv_bfloat16* Bhg = Bhi + (size_t)(n0 + tid) * H_;
    const __nv_bfloat16* Blg = Blo + (size_t)(n0 + tid) * H_;

    const float* Xg  = buf + OFF_XG + (size_t)r * B_ * T_ * G4_;
    float*       cst = buf + OFF_C + (size_t)r * B_ * H_;
    float*       Yst = buf + OFF_Y + (size_t)r * B_ * T_ * H_;
    float*       hB  = buf + OFF_H;
    const size_t HBUF = 4ull * B_ * H_;

    unsigned* sync = (unsigned*)(buf + OFF_SYNC);

    uint32_t aSt = (uint32_t)((tid >> 1) * PAD + (tid & 1) * 16) * 2;
    uint32_t bSt = (uint32_t)(tid * PAD) * 2;
    uint32_t aLd = (uint32_t)((lane & 15) * PAD + ((lane >> 4) << 3)) * 2;
    uint32_t bLd = (uint32_t)(((lane & 7) + ((lane & 16) >> 1)) * PAD + (lane & 8)) * 2;

    for (int t = 0; t < T_; t++) {
        const float* hin  = hB + (size_t)(t & 1) * HBUF + (size_t)r * B_ * H_;
        float*       hout = hB + (size_t)((t + 1) & 1) * HBUF + (size_t)r * B_ * H_;
        const float* Ag = hin + (size_t)(m0 + (tid >> 1)) * H_ + (tid & 1) * 16;

        float acc[4][4][4] = {};
        gemm_k(Ag, Bhg, Blg, H_ / KC, smem_raw, sb, aSt, bSt, aLd, bLd, wid, acc);

        // fused LSTM cell epilogue (permuted cols n' = 4j+g; g:0=i,1=j,2=f,3=o)
#pragma unroll
        for (int mt = 0; mt < 4; mt++) {
            int b = m0 + mt * 16 + (lane >> 2);
#pragma unroll
            for (int nt = 0; nt < 4; nt++) {
                float fo0 = __shfl_xor_sync(0xffffffffu, acc[mt][nt][0], 1);
                float fo1 = __shfl_xor_sync(0xffffffffu, acc[mt][nt][1], 1);
                float fo2 = __shfl_xor_sync(0xffffffffu, acc[mt][nt][2], 1);
                float fo3 = __shfl_xor_sync(0xffffffffu, acc[mt][nt][3], 1);
                if (!(lane & 1)) {
#pragma unroll
                    for (int half = 0; half < 2; half++) {
                        int bb = b + half * 8;
                        float gi = half ? acc[mt][nt][2] : acc[mt][nt][0];
                        float gj = half ? acc[mt][nt][3] : acc[mt][nt][1];
                        float gf = half ? fo2 : fo0;
                        float go = half ? fo3 : fo1;
                        int c0 = n0 + wid * 32 + nt * 8 + (lane & 3) * 2;
                        int j = c0 >> 2;
                        float4 x = *(const float4*)(Xg + ((size_t)bb * T_ + t) * G4_ + c0);
                        gi += x.x; gj += x.y; gf += x.z; go += x.w;
                        size_t ci = (size_t)bb * H_ + j;
                        float yv = 0.f;
                        if (t < sl[bb]) {
                            float cc = cst[ci];
                            float cn = cc * sigf(gf + 1.f) + sigf(gi) * ftanh(gj);
                            float hn = ftanh(cn) * sigf(go);
                            cst[ci] = cn;
                            hout[ci] = hn;
                            yv = hn;
                        } else {
                            hout[ci] = __ldcg(hin + ci);
                        }
                        Yst[((size_t)bb * T_ + t) * H_ + j] = yv;
                    }
                }
            }
        }
        gbar(sync + 0, (volatile unsigned*)(sync + 1), (unsigned)(t + 1), 128u);
    }
}

// ---------------- persistent attention scan (one launch, 128 CTAs) ----------
__global__ void __launch_bounds__(128) k_att_persist(
    const float* __restrict__ wv,
    const int* __restrict__ s1, const int* __restrict__ s2) {
    extern __shared__ __align__(16) char smem_raw[];
    uint32_t sb = smem_u32(smem_raw);
    float* smf = (float*)smem_raw;   // reused after GEMM phase: su[512], spt[512], sc[64]
    float* buf = d_buf;
    int tid = threadIdx.x, lane = tid & 31, wid = tid >> 5;
    int blk = blockIdx.x;

    // GEMM decode: 4 ks x 4 mt x 8 nt
    int ks  = blk & 3;
    int mt_ = (blk >> 2) & 3;
    int nt_ = blk >> 4;
    int m0 = mt_ * TM, n0 = nt_ * TN, kst = ks * 128;

    const __nv_bfloat16* WcS = (const __nv_bfloat16*)(buf + OFF_WCS);
    const __nv_bfloat16* Bhg = WcS + (size_t)(n0 + tid) * H_ + kst;
    const __nv_bfloat16* Blg = WcS + 2ull * H_ * H_ + (size_t)(n0 + tid) * H_ + kst;

    float* rbuf = buf + OFF_R;
    float* uPt4 = buf + OFF_UPT;
    float* rL   = buf + OFF_RL;
    const float* WyY = buf + OFF_WYY;
    const float* HWy = buf + OFF_HWY;
    const float* Yb  = buf + OFF_Y;
    unsigned* sync = (unsigned*)(buf + OFF_SYNC);

    uint32_t aSt = (uint32_t)((tid >> 1) * PAD + (tid & 1) * 16) * 2;
    uint32_t bSt = (uint32_t)(tid * PAD) * 2;
    uint32_t aLd = (uint32_t)((lane & 15) * PAD + ((lane >> 4) << 3)) * 2;
    uint32_t bLd = (uint32_t)(((lane & 7) + ((lane & 16) >> 1)) * PAD + (lane & 8)) * 2;

    for (int t = 0; t < T_; t++) {
        // ---- phase G: uPt4[ks] = rbuf(kslice) @ Wc ----
        {
            const float* Ag = rbuf + (size_t)(m0 + (tid >> 1)) * H_ + kst + (tid & 1) * 16;
            float acc[4][4][4] = {};
            gemm_k(Ag, Bhg, Blg, 4, smem_raw, sb, aSt, bSt, aLd, bLd, wid, acc);
            float* Cb = uPt4 + (size_t)ks * 256 * 1024;
#pragma unroll
            for (int mt = 0; mt < 4; mt++) {
                int r = m0 + mt * 16 + (lane >> 2);
#pragma unroll
                for (int nt = 0; nt < 4; nt++) {
                    int c = n0 + wid * 32 + nt * 8 + (lane & 3) * 2;
                    *(float2*)(Cb + (size_t)r * 1024 + c) =
                        make_float2(acc[mt][nt][0], acc[mt][nt][1]);
                    *(float2*)(Cb + (size_t)(r + 8) * 1024 + c) =
                        make_float2(acc[mt][nt][2], acc[mt][nt][3]);
                }
            }
        }
        gbar(sync + 2, (volatile unsigned*)(sync + 3), (unsigned)(2 * t + 1), 128u);

        // ---- phase A: two (a,b) pairs per CTA ----
#pragma unroll
        for (int pi = 0; pi < 2; pi++) {
            int p = blk * 2 + pi;         // p = a*128 + b
            int a = p >> 7, b = p & 127;
            float* su  = smf;
            float* spt = smf + 512;
            float* sc  = smf + 1024;
            // preamble: sum 4 split-K partials + HWy
            const float* hb = HWy + (size_t)a * B_ * T_ * H_ + ((size_t)b * T_ + t) * H_;
#pragma unroll
            for (int q = 0; q < 4; q++) {
                int h = tid + q * 128;
                float s0 = 0.f, s1v = 0.f;
#pragma unroll
                for (int k = 0; k < 4; k++) {
                    const float* up = uPt4 + ((size_t)k * 256 + p) * 1024;
                    s0  += __ldcg(up + h);
                    s1v += __ldcg(up + 512 + h);
                }
                su[h]  = s0 + __ldg(hb + h);
                spt[h] = s1v;
            }
            __syncthreads();
            // scores: 4 warps x 16 t2
            const float* WyYb = WyY + (size_t)a * B_ * T_ * H_ + (size_t)b * T_ * H_;
            int slm = (a ? s2[b] : s1[b]);
#pragma unroll
            for (int q = 0; q < 16; q++) {
                int t2 = wid * 16 + q;
                const float* row = WyYb + (size_t)t2 * H_;
                float s = 0.f;
#pragma unroll 4
                for (int hh = lane; hh < H_; hh += 32)
                    s += tanha(__ldg(row + hh) + su[hh]) * __ldg(wv + hh);
                for (int o = 16; o; o >>= 1) s += __shfl_xor_sync(0xffffffffu, s, o);
                if (lane == 0) sc[t2] = s + (t2 < slm ? 0.f : -10000.f);
            }
            __syncthreads();
            if (wid == 0) {
                float v1 = sc[lane], v2 = sc[lane + 32];
                float m = fmaxf(v1, v2);
                for (int o = 16; o; o >>= 1) m = fmaxf(m, __shfl_xor_sync(0xffffffffu, m, o));
                float e1 = __expf(v1 - m), e2 = __expf(v2 - m);
                float s = e1 + e2;
                for (int o = 16; o; o >>= 1) s += __shfl_xor_sync(0xffffffffu, s, o);
                float inv = __fdividef(1.f, s);
                sc[lane] = e1 * inv;
                sc[lane + 32] = e2 * inv;
            }
            __syncthreads();
            // context + r update: 128 threads x 4 h
            const float* Yp = Yb + (size_t)(a ? 2 : 0) * B_ * T_ * H_ + (size_t)b * T_ * H_;
            int sl2 = a ? s1[b] : s2[b];
#pragma unroll
            for (int q = 0; q < 4; q++) {
                int h = tid + q * 128;
                float accv = 0.f;
#pragma unroll
                for (int t2 = 0; t2 < T_; t2++)
                    accv += sc[t2] * __ldg(Yp + (size_t)t2 * H_ + h);
                float rn = accv + ftanh(spt[h]);
                if (t == sl2 - 1) rL[(size_t)p * H_ + h] = rn;
                rbuf[(size_t)p * H_ + h] = rn;
            }
            __syncthreads();
        }
        gbar(sync + 2, (volatile unsigned*)(sync + 3), (unsigned)(2 * t + 2), 128u);
    }
}

// ---------------- final projection ----------------
__global__ void __launch_bounds__(512) k_final(
    const float* __restrict__ rL, const float* __restrict__ hfin,
    const float* __restrict__ Wp, const float* __restrict__ Wx,
    const float* __restrict__ U, const float* __restrict__ bU,
    float* __restrict__ out) {
    int b = blockIdx.x;
    int tid = threadIdx.x;
    __shared__ float s_in[4][512];
    __shared__ float s_sum[512];
    __shared__ float red0[16], red1[16];
    s_in[0][tid] = rL[(size_t)b * H_ + tid];
    s_in[1][tid] = hfin[((size_t)1 * B_ + b) * H_ + tid];
    s_in[2][tid] = rL[((size_t)B_ + b) * H_ + tid];
    s_in[3][tid] = hfin[((size_t)3 * B_ + b) * H_ + tid];
    __syncthreads();
    float acc0 = 0.f, acc1 = 0.f;
    for (int k = 0; k < H_; k++) {
        float wp = Wp[(size_t)k * H_ + tid];
        float wx = Wx[(size_t)k * H_ + tid];
        acc0 += s_in[0][k] * wp + s_in[1][k] * wx;
        acc1 += s_in[2][k] * wp + s_in[3][k] * wx;
    }
    s_sum[tid] = ftanh(acc0) + ftanh(acc1);
    __syncthreads();
    float p0 = s_sum[tid] * U[(size_t)tid * 2 + 0];
    float p1 = s_sum[tid] * U[(size_t)tid * 2 + 1];
    for (int o = 16; o; o >>= 1) {
        p0 += __shfl_xor_sync(0xffffffffu, p0, o);
        p1 += __shfl_xor_sync(0xffffffffu, p1, o);
    }
    int wp_ = tid >> 5;
    if ((tid & 31) == 0) { red0[wp_] = p0; red1[wp_] = p1; }
    __syncthreads();
    if (tid < 16) {
        p0 = red0[tid]; p1 = red1[tid];
        for (int o = 8; o; o >>= 1) {
            p0 += __shfl_xor_sync(0x0000ffffu, p0, o);
            p1 += __shfl_xor_sync(0x0000ffffu, p1, o);
        }
        if (tid == 0) {
            out[b * 2 + 0] = p0 + bU[0];
            out[b * 2 + 1] = p1 + bU[1];
        }
    }
}

// ---------------- host ----------------
extern "C" void kernel_launch(void* const* d_in, const int* in_sizes, int n_in,
                              void* d_out, int out_size) {
    (void)in_sizes; (void)n_in; (void)out_size;
    const int*   tokens1 = (const int*)d_in[0];
    const int*   tokens2 = (const int*)d_in[1];
    const int*   seqlen1 = (const int*)d_in[2];
    const int*   seqlen2 = (const int*)d_in[3];
    const float* emb = (const float*)d_in[4];
    const float* W1  = (const float*)d_in[5];
    const float* b1  = (const float*)d_in[6];
    const float* W2  = (const float*)d_in[7];
    const float* b2  = (const float*)d_in[8];
    const float* Wy  = (const float*)d_in[9];
    const float* Wh  = (const float*)d_in[10];
    const float* Wr  = (const float*)d_in[11];
    const float* wv  = (const float*)d_in[12];
    const float* Wt  = (const float*)d_in[13];
    const float* Wp  = (const float*)d_in[14];
    const float* Wx  = (const float*)d_in[15];
    const float* U   = (const float*)d_in[16];
    const float* bU  = (const float*)d_in[17];
    float* out = (float*)d_out;

    cudaFuncSetAttribute(mm_gemm, cudaFuncAttributeMaxDynamicSharedMemorySize, SMEM_MM);
    cudaFuncSetAttribute(k_lstm_persist, cudaFuncAttributeMaxDynamicSharedMemorySize, SMEM_MM);
    cudaFuncSetAttribute(k_att_persist, cudaFuncAttributeMaxDynamicSharedMemorySize, SMEM_MM);

    float* buf = nullptr;
    cudaGetSymbolAddress((void**)&buf, d_buf);
    float* e    = buf + OFF_E;
    float* Xg   = buf + OFF_XG;
    float* Yb   = buf + OFF_Y;
    float* hBuf = buf + OFF_H;
    float* WyY  = buf + OFF_WYY;
    float* HWy  = buf + OFF_HWY;
    float* rbuf = buf + OFF_R;
    float* rL   = buf + OFF_RL;
    float* bP   = buf + OFF_BP;
    __nv_bfloat16* WxS = (__nv_bfloat16*)(buf + OFF_WXS);
    __nv_bfloat16* WyS = (__nv_bfloat16*)(buf + OFF_WYS);
    __nv_bfloat16* WhA = (__nv_bfloat16*)(buf + OFF_WHA);

    k_prep<<<1024, 256>>>(W1, W2, Wy, Wh, Wr, Wt, b1, b2);
    k_gather<<<2048, 256>>>(e, tokens1, tokens2, emb);
    k_zero<<<512, 256>>>(hBuf, 12ull * B_ * H_);       // h ping-pong + c
    k_zero<<<128, 256>>>(rbuf, 256ull * H_);
    k_zero<<<1, 32>>>(buf + OFF_SYNC, 16);

    const int iidx[4] = {0, 1, 1, 0}, widx[4] = {0, 1, 0, 1};

    // X-part: Xg[r] = E_i(r) @ WxS_w(r) + bP_w(r)
    {
        MP p = {};
        for (int r = 0; r < 4; r++) {
            p.z[r].A    = e + (size_t)iidx[r] * B_ * T_ * KPX;
            p.z[r].Bhi  = WxS + (size_t)(widx[r] * 2 + 0) * G4_ * KPX;
            p.z[r].Blo  = WxS + (size_t)(widx[r] * 2 + 1) * G4_ * KPX;
            p.z[r].C    = Xg + (size_t)r * B_ * T_ * G4_;
            p.z[r].bias = bP + (size_t)widx[r] * G4_;
        }
        p.Klen = KPX; p.lda = KPX; p.ldb = KPX; p.ldc = G4_;
        mm_gemm<<<dim3(G4_ / TN, (B_ * T_) / TM, 4), 128, SMEM_MM>>>(p);
    }

    // LSTM scan: ONE persistent launch
    k_lstm_persist<<<128, 128, SMEM_MM>>>(seqlen1, seqlen2);

    // WyY (runs 0,2 @ Wy) + HWy (runs 1,3 @ Wh)
    {
        MP p = {};
        const int runs[4] = {0, 2, 1, 3};
        for (int q = 0; q < 4; q++) {
            p.z[q].A   = Yb + (size_t)runs[q] * B_ * T_ * H_;
            p.z[q].Bhi = (q < 2 ? WyS : WhA);
            p.z[q].Blo = (q < 2 ? WyS : WhA) + (size_t)H_ * H_;
            p.z[q].C   = (q < 2 ? WyY + (size_t)q * B_ * T_ * H_
                                : HWy + (size_t)(q - 2) * B_ * T_ * H_);
            p.z[q].bias = nullptr;
        }
        p.Klen = H_; p.lda = H_; p.ldb = H_; p.ldc = H_;
        mm_gemm<<<dim3(H_ / TN, (B_ * T_) / TM, 4), 128, SMEM_MM>>>(p);
    }

    // Attention scan: ONE persistent launch
    k_att_persist<<<128, 128, SMEM_MM>>>(wv, seqlen1, seqlen2);

    k_final<<<B_, 512>>>(rL, hBuf, Wp, Wx, U, bU, out);
}

// round 6
// speedup vs baseline: 1.3727x; 1.0865x over previous
#include <cuda_runtime.h>
#include <cuda_bf16.h>
#include <math.h>
#include <stdint.h>

#define B_   128
#define T_   64
#define D_   300
#define KPX  320
#define H_   512
#define G4_  2048

#define TM 64
#define TN 128
#define KC 32
#define PAD 40
#define A_BASE(term,stage) ((uint32_t)(((term)*2+(stage))*5120))
#define B_BASE(term,stage) ((uint32_t)(20480u + ((term)*2+(stage))*10240u))
static constexpr int SMEM_MM = 61440;

__device__ __forceinline__ uint32_t smem_u32(const void* p) {
    uint32_t a;
    asm("{ .reg .u64 t; cvta.to.shared.u64 t, %1; cvt.u32.u64 %0, t; }" : "=r"(a) : "l"(p));
    return a;
}
#define CP_ASYNC16(dst, src) \
    asm volatile("cp.async.cg.shared.global [%0], [%1], 16;" :: "r"(dst), "l"(src))
#define CP_COMMIT() asm volatile("cp.async.commit_group;" ::: "memory")
#define CP_WAIT0()  asm volatile("cp.async.wait_group 0;" ::: "memory")
#define LDSM4(r0, r1, r2, r3, addr) \
    asm volatile("ldmatrix.sync.aligned.m8n8.x4.shared.b16 {%0,%1,%2,%3}, [%4];" \
                 : "=r"(r0), "=r"(r1), "=r"(r2), "=r"(r3) : "r"(addr))
#define MMA16816(c, a, b0, b1) \
    asm volatile("mma.sync.aligned.m16n8k16.row.col.f32.bf16.bf16.f32 " \
                 "{%0,%1,%2,%3}, {%4,%5,%6,%7}, {%8,%9}, {%0,%1,%2,%3};" \
                 : "+f"((c)[0]), "+f"((c)[1]), "+f"((c)[2]), "+f"((c)[3]) \
                 : "r"((a)[0]), "r"((a)[1]), "r"((a)[2]), "r"((a)[3]), \
                   "r"(b0), "r"(b1))

__device__ __forceinline__ float sigf(float x) { return __fdividef(1.f, 1.f + __expf(-x)); }
__device__ __forceinline__ float ftanh(float x) { return 1.f - __fdividef(2.f, __expf(2.f * x) + 1.f); }
__device__ __forceinline__ float tanha(float x) {
    float y; asm("tanh.approx.f32 %0, %1;" : "=f"(y) : "f"(x)); return y;
}

// ---------------- scratch layout (float units) ----------------
static constexpr size_t OFF_E    = 0;
static constexpr size_t OFF_XG   = OFF_E   + 2ull * B_ * T_ * KPX;
static constexpr size_t OFF_Y    = OFF_XG  + 4ull * B_ * T_ * G4_;
static constexpr size_t OFF_H    = OFF_Y   + 4ull * B_ * T_ * H_;
static constexpr size_t OFF_C    = OFF_H   + 2ull * 4 * B_ * H_;
static constexpr size_t OFF_WYY  = OFF_C   + 4ull * B_ * H_;
static constexpr size_t OFF_HWY  = OFF_WYY + 2ull * B_ * T_ * H_;
static constexpr size_t OFF_UPT  = OFF_HWY + 2ull * B_ * T_ * H_;       // [4 ks][256][1024]
static constexpr size_t OFF_R    = OFF_UPT + 4ull * 256 * 1024;         // [256][512]
static constexpr size_t OFF_RL   = OFF_R   + 256ull * H_;
static constexpr size_t OFF_BP   = OFF_RL  + 256ull * H_;
static constexpr size_t OFF_WXS  = OFF_BP  + 2ull * G4_;
static constexpr size_t OFF_WHS  = OFF_WXS + (2ull * 2 * G4_ * KPX) / 2;
static constexpr size_t OFF_WYS  = OFF_WHS + (2ull * 2 * G4_ * H_) / 2;
static constexpr size_t OFF_WHA  = OFF_WYS + (2ull * H_ * H_) / 2;
static constexpr size_t OFF_WCS  = OFF_WHA + (2ull * H_ * H_) / 2;
static constexpr size_t OFF_SYNC = OFF_WCS + (2ull * 2 * H_ * H_) / 2;  // 16 words
static constexpr size_t TOTAL_F  = OFF_SYNC + 16;

__device__ __align__(256) float d_buf[TOTAL_F];

__device__ __forceinline__ void split_store(float v, __nv_bfloat16* hi, __nv_bfloat16* lo) {
    __nv_bfloat16 h = __float2bfloat16_rn(v);
    *hi = h;
    *lo = __float2bfloat16_rn(v - __bfloat162float(h));
}

// ---------------- grid barrier: gpu-scope release/acquire -----------------
__device__ __forceinline__ void gbar(unsigned* cnt, unsigned* rel,
                                     unsigned seq, unsigned ncta) {
    __syncthreads();
    if (threadIdx.x == 0) {
        unsigned old;
        asm volatile("fence.acq_rel.gpu;" ::: "memory");
        asm volatile("atom.relaxed.gpu.global.add.u32 %0, [%1], 1;"
                     : "=r"(old) : "l"(cnt) : "memory");
        if (old + 1u == ncta * seq) {
            asm volatile("st.release.gpu.global.u32 [%0], %1;"
                         :: "l"(rel), "r"(seq) : "memory");
        }
        unsigned v;
        do {
            asm volatile("ld.acquire.gpu.global.u32 %0, [%1];"
                         : "=r"(v) : "l"(rel) : "memory");
        } while (v < seq);
    }
    __syncthreads();
}

// ---------------- prep: weight splits + ALL zero-init (no k_zero launches) --
__global__ void k_prep(const float* __restrict__ W1, const float* __restrict__ W2,
                       const float* __restrict__ Wy, const float* __restrict__ Wh,
                       const float* __restrict__ Wr, const float* __restrict__ Wt,
                       const float* __restrict__ b1, const float* __restrict__ b2) {
    float* buf = d_buf;
    __nv_bfloat16* WxS = (__nv_bfloat16*)(buf + OFF_WXS);
    __nv_bfloat16* WhS = (__nv_bfloat16*)(buf + OFF_WHS);
    __nv_bfloat16* WyS = (__nv_bfloat16*)(buf + OFF_WYS);
    __nv_bfloat16* WhA = (__nv_bfloat16*)(buf + OFF_WHA);
    __nv_bfloat16* WcS = (__nv_bfloat16*)(buf + OFF_WCS);
    float* bP = buf + OFF_BP;

    const size_t R1 = 2ull * G4_ * KPX;
    const size_t R2 = 2ull * G4_ * H_;
    const size_t R3 = (size_t)H_ * H_;
    const size_t R4 = (size_t)H_ * H_;
    const size_t R5 = 2ull * H_ * H_;
    const size_t R6 = 2ull * G4_;
    const size_t R7 = 12ull * B_ * H_;      // h ping-pong + c
    const size_t R8 = 256ull * H_;          // rbuf
    const size_t R9 = 16;                   // sync
    const size_t TOT = R1 + R2 + R3 + R4 + R5 + R6 + R7 + R8 + R9;
    size_t stride = (size_t)gridDim.x * blockDim.x;
    for (size_t id = (size_t)blockIdx.x * blockDim.x + threadIdx.x; id < TOT; id += stride) {
        size_t i = id;
        if (i < R1) {
            int w = (int)(i / ((size_t)G4_ * KPX));
            size_t rem = i % ((size_t)G4_ * KPX);
            int np = (int)(rem / KPX), k = (int)(rem % KPX);
            int col = (np & 3) * H_ + (np >> 2);
            const float* W = w ? W2 : W1;
            float v = (k < D_) ? W[(size_t)k * G4_ + col] : 0.f;
            size_t o = ((size_t)(w * 2) * G4_ + np) * KPX + k;
            split_store(v, WxS + o, WxS + o + (size_t)G4_ * KPX);
            continue;
        }
        i -= R1;
        if (i < R2) {
            int w = (int)(i / ((size_t)G4_ * H_));
            size_t rem = i % ((size_t)G4_ * H_);
            int np = (int)(rem / H_), k = (int)(rem % H_);
            int col = (np & 3) * H_ + (np >> 2);
            const float* W = w ? W2 : W1;
            float v = W[(size_t)(D_ + k) * G4_ + col];
            size_t o = ((size_t)(w * 2) * G4_ + np) * H_ + k;
            split_store(v, WhS + o, WhS + o + (size_t)G4_ * H_);
            continue;
        }
        i -= R2;
        if (i < R3) {
            int n = (int)(i / H_), k = (int)(i % H_);
            size_t o = (size_t)n * H_ + k;
            split_store(Wy[(size_t)k * H_ + n], WyS + o, WyS + o + (size_t)H_ * H_);
            continue;
        }
        i -= R3;
        if (i < R4) {
            int n = (int)(i / H_), k = (int)(i % H_);
            size_t o = (size_t)n * H_ + k;
            split_store(Wh[(size_t)k * H_ + n], WhA + o, WhA + o + (size_t)H_ * H_);
            continue;
        }
        i -= R4;
        if (i < R5) {
            int n = (int)(i / H_), k = (int)(i % H_);
            float v = (n < H_) ? Wr[(size_t)k * H_ + n] : Wt[(size_t)k * H_ + (n - H_)];
            size_t o = (size_t)n * H_ + k;
            split_store(v, WcS + o, WcS + o + 2ull * H_ * H_);
            continue;
        }
        i -= R5;
        if (i < R6) {
            int w = (int)(i / G4_), np = (int)(i % G4_);
            int col = (np & 3) * H_ + (np >> 2);
            bP[i] = (w ? b2 : b1)[col];
            continue;
        }
        i -= R6;
        if (i < R7) { (buf + OFF_H)[i] = 0.f; continue; }
        i -= R7;
        if (i < R8) { (buf + OFF_R)[i] = 0.f; continue; }
        i -= R8;
        (buf + OFF_SYNC)[i] = 0.f;
    }
}

__global__ void k_gather(float* __restrict__ e, const int* __restrict__ t1,
                         const int* __restrict__ t2, const float* __restrict__ emb) {
    size_t total = 2ull * B_ * T_ * KPX;
    size_t stride = (size_t)gridDim.x * blockDim.x;
    for (size_t i = (size_t)blockIdx.x * blockDim.x + threadIdx.x; i < total; i += stride) {
        int which = (int)(i / ((size_t)B_ * T_ * KPX));
        size_t rem = i % ((size_t)B_ * T_ * KPX);
        int bt = (int)(rem / KPX), k = (int)(rem % KPX);
        int tok = (which ? t2 : t1)[bt];
        e[i] = (k < D_) ? emb[(size_t)tok * D_ + k] : 0.f;
    }
}

// ---------------------------------------------------------------------------
// Core K-loop: acc += A(fp32, ldcg) x B(bf16 hi/lo), 64x128 tile, 128 threads.
// ---------------------------------------------------------------------------
__device__ __forceinline__ void gemm_k(
    const float* __restrict__ Ag, const __nv_bfloat16* __restrict__ Bhg,
    const __nv_bfloat16* __restrict__ Blg, int nch,
    char* smem_raw, uint32_t sb,
    uint32_t aSt, uint32_t bSt, uint32_t aLd, uint32_t bLd,
    int wid, float acc[4][4][4]) {
    float fA[16];
    {
#pragma unroll
        for (int q = 0; q < 4; q++) {
            CP_ASYNC16(sb + B_BASE(0, 0) + bSt + q * 16, Bhg + q * 8);
            CP_ASYNC16(sb + B_BASE(1, 0) + bSt + q * 16, Blg + q * 8);
        }
        CP_COMMIT();
        const float4* s4 = (const float4*)Ag;
#pragma unroll
        for (int q = 0; q < 4; q++) {
            float4 v = __ldcg(s4 + q);
            fA[4 * q] = v.x; fA[4 * q + 1] = v.y; fA[4 * q + 2] = v.z; fA[4 * q + 3] = v.w;
        }
        ushort hi[16], lo[16];
#pragma unroll
        for (int q = 0; q < 16; q++) {
            __nv_bfloat16 hb = __float2bfloat16_rn(fA[q]);
            __nv_bfloat16 lb = __float2bfloat16_rn(fA[q] - __bfloat162float(hb));
            hi[q] = *(ushort*)&hb; lo[q] = *(ushort*)&lb;
        }
        *(uint4*)(smem_raw + A_BASE(0, 0) + aSt)      = *(uint4*)(hi);
        *(uint4*)(smem_raw + A_BASE(0, 0) + aSt + 16) = *(uint4*)(hi + 8);
        *(uint4*)(smem_raw + A_BASE(1, 0) + aSt)      = *(uint4*)(lo);
        *(uint4*)(smem_raw + A_BASE(1, 0) + aSt + 16) = *(uint4*)(lo + 8);
        CP_WAIT0();
        __syncthreads();
    }
    for (int ch = 0; ch < nch; ch++) {
        int s = ch & 1, ns = s ^ 1;
        bool more = (ch + 1) < nch;
        if (more) {
            const __nv_bfloat16* bh2 = Bhg + (ch + 1) * KC;
            const __nv_bfloat16* bl2 = Blg + (ch + 1) * KC;
#pragma unroll
            for (int q = 0; q < 4; q++) {
                CP_ASYNC16(sb + B_BASE(0, ns) + bSt + q * 16, bh2 + q * 8);
                CP_ASYNC16(sb + B_BASE(1, ns) + bSt + q * 16, bl2 + q * 8);
            }
            CP_COMMIT();
            const float4* s4 = (const float4*)(Ag + (ch + 1) * KC);
#pragma unroll
            for (int q = 0; q < 4; q++) {
                float4 v = __ldcg(s4 + q);
                fA[4 * q] = v.x; fA[4 * q + 1] = v.y; fA[4 * q + 2] = v.z; fA[4 * q + 3] = v.w;
            }
        }
#pragma unroll
        for (int h16 = 0; h16 < 2; h16++) {
            uint32_t kb = (uint32_t)h16 * 32;
            uint32_t bh[8], bl[8];
#pragma unroll
            for (int g = 0; g < 2; g++) {
                uint32_t rowb = (uint32_t)((wid * 32 + g * 16) * PAD) * 2;
                LDSM4(bh[g * 4 + 0], bh[g * 4 + 1], bh[g * 4 + 2], bh[g * 4 + 3],
                      sb + B_BASE(0, s) + bLd + rowb + kb);
                LDSM4(bl[g * 4 + 0], bl[g * 4 + 1], bl[g * 4 + 2], bl[g * 4 + 3],
                      sb + B_BASE(1, s) + bLd + rowb + kb);
            }
#pragma unroll
            for (int mt = 0; mt < 4; mt++) {
                uint32_t ah[4], al[4];
                uint32_t rowa = (uint32_t)(mt * 16 * PAD) * 2;
                LDSM4(ah[0], ah[1], ah[2], ah[3], sb + A_BASE(0, s) + aLd + rowa + kb);
                LDSM4(al[0], al[1], al[2], al[3], sb + A_BASE(1, s) + aLd + rowa + kb);
#pragma unroll
                for (int nt = 0; nt < 4; nt++) {
                    int bi = (nt >> 1) * 4 + (nt & 1) * 2;
                    MMA16816(acc[mt][nt], ah, bh[bi], bh[bi + 1]);
                    MMA16816(acc[mt][nt], ah, bl[bi], bl[bi + 1]);
                    MMA16816(acc[mt][nt], al, bh[bi], bh[bi + 1]);
                }
            }
        }
        if (more) {
            ushort hi[16], lo[16];
#pragma unroll
            for (int q = 0; q < 16; q++) {
                __nv_bfloat16 hb = __float2bfloat16_rn(fA[q]);
                __nv_bfloat16 lb = __float2bfloat16_rn(fA[q] - __bfloat162float(hb));
                hi[q] = *(ushort*)&hb; lo[q] = *(ushort*)&lb;
            }
            *(uint4*)(smem_raw + A_BASE(0, ns) + aSt)      = *(uint4*)(hi);
            *(uint4*)(smem_raw + A_BASE(0, ns) + aSt + 16) = *(uint4*)(hi + 8);
            *(uint4*)(smem_raw + A_BASE(1, ns) + aSt)      = *(uint4*)(lo);
            *(uint4*)(smem_raw + A_BASE(1, ns) + aSt + 16) = *(uint4*)(lo + 8);
            CP_WAIT0();
        }
        __syncthreads();
    }
}

// ---------------- bulk GEMM ----------------
struct MZ {
    const float*         A;
    const __nv_bfloat16* Bhi;
    const __nv_bfloat16* Blo;
    float*               C;
    const float*         bias;
};
struct MP {
    MZ z[4];
    int Klen, lda, ldb, ldc;
};

__global__ void __launch_bounds__(128) mm_gemm(MP p) {
    extern __shared__ __align__(16) char smem_raw[];
    uint32_t sb = smem_u32(smem_raw);
    const MZ z = p.z[blockIdx.z];
    int tid = threadIdx.x, lane = tid & 31, wid = tid >> 5;
    int n0 = blockIdx.x * TN, m0 = blockIdx.y * TM;

    const float*         Ag  = z.A   + (size_t)(m0 + (tid >> 1)) * p.lda + (tid & 1) * 16;
    const __nv_bfloat16* Bhg = z.Bhi + (size_t)(n0 + tid) * p.ldb;
    const __nv_bfloat16* Blg = z.Blo + (size_t)(n0 + tid) * p.ldb;
    uint32_t aSt = (uint32_t)((tid >> 1) * PAD + (tid & 1) * 16) * 2;
    uint32_t bSt = (uint32_t)(tid * PAD) * 2;
    uint32_t aLd = (uint32_t)((lane & 15) * PAD + ((lane >> 4) << 3)) * 2;
    uint32_t bLd = (uint32_t)(((lane & 7) + ((lane & 16) >> 1)) * PAD + (lane & 8)) * 2;

    float acc[4][4][4] = {};
    gemm_k(Ag, Bhg, Blg, p.Klen / KC, smem_raw, sb, aSt, bSt, aLd, bLd, wid, acc);

#pragma unroll
    for (int mt = 0; mt < 4; mt++) {
        int r = m0 + mt * 16 + (lane >> 2);
#pragma unroll
        for (int nt = 0; nt < 4; nt++) {
            int c = n0 + wid * 32 + nt * 8 + (lane & 3) * 2;
            float b0 = 0.f, b1 = 0.f;
            if (z.bias) { b0 = z.bias[c]; b1 = z.bias[c + 1]; }
            *(float2*)(z.C + (size_t)r * p.ldc + c) =
                make_float2(acc[mt][nt][0] + b0, acc[mt][nt][1] + b1);
            *(float2*)(z.C + (size_t)(r + 8) * p.ldc + c) =
                make_float2(acc[mt][nt][2] + b0, acc[mt][nt][3] + b1);
        }
    }
}

// ---------------- persistent LSTM scan ----------------
__global__ void __launch_bounds__(128) k_lstm_persist(
    const int* __restrict__ s1, const int* __restrict__ s2) {
    extern __shared__ __align__(16) char smem_raw[];
    uint32_t sb = smem_u32(smem_raw);
    float* buf = d_buf;
    int tid = threadIdx.x, lane = tid & 31, wid = tid >> 5;
    int blk = blockIdx.x;
    int r  = blk >> 5;
    int mt_ = (blk >> 4) & 1;
    int nt_ = blk & 15;
    int n0 = nt_ * TN, m0 = mt_ * TM;
    int widx = (r == 0 || r == 2) ? 0 : 1;
    const int* sl = (r == 0 || r == 3) ? s1 : s2;

    const __nv_bfloat16* WhS = (const __nv_bfloat16*)(buf + OFF_WHS);
    const __nv_bfloat16* Bhg = WhS + (size_t)(widx * 2 + 0) * G4_ * H_ + (size_t)(n0 + tid) * H_;
    const __nv_bfloat16* Blg = WhS + (size_t)(widx * 2 + 1) * G4_ * H_ + (size_t)(n0 + tid) * H_;

    const float* Xg  = buf + OFF_XG + (size_t)r * B_ * T_ * G4_;
    float*       cst = buf + OFF_C + (size_t)r * B_ * H_;
    float*       Yst = buf + OFF_Y + (size_t)r * B_ * T_ * H_;
    float*       hB  = buf + OFF_H;
    const size_t HBUF = 4ull * B_ * H_;

    unsigned* sync = (unsigned*)(buf + OFF_SYNC);

    uint32_t aSt = (uint32_t)((tid >> 1) * PAD + (tid & 1) * 16) * 2;
    uint32_t bSt = (uint32_t)(tid * PAD) * 2;
    uint32_t aLd = (uint32_t)((lane & 15) * PAD + ((lane >> 4) << 3)) * 2;
    uint32_t bLd = (uint32_t)(((lane & 7) + ((lane & 16) >> 1)) * PAD + (lane & 8)) * 2;

    for (int t = 0; t < T_; t++) {
        const float* hin  = hB + (size_t)(t & 1) * HBUF + (size_t)r * B_ * H_;
        float*       hout = hB + (size_t)((t + 1) & 1) * HBUF + (size_t)r * B_ * H_;
        const float* Ag = hin + (size_t)(m0 + (tid >> 1)) * H_ + (tid & 1) * 16;

        float acc[4][4][4] = {};
        gemm_k(Ag, Bhg, Blg, H_ / KC, smem_raw, sb, aSt, bSt, aLd, bLd, wid, acc);

#pragma unroll
        for (int mt = 0; mt < 4; mt++) {
            int b = m0 + mt * 16 + (lane >> 2);
#pragma unroll
            for (int nt = 0; nt < 4; nt++) {
                float fo0 = __shfl_xor_sync(0xffffffffu, acc[mt][nt][0], 1);
                float fo1 = __shfl_xor_sync(0xffffffffu, acc[mt][nt][1], 1);
                float fo2 = __shfl_xor_sync(0xffffffffu, acc[mt][nt][2], 1);
                float fo3 = __shfl_xor_sync(0xffffffffu, acc[mt][nt][3], 1);
                if (!(lane & 1)) {
#pragma unroll
                    for (int half = 0; half < 2; half++) {
                        int bb = b + half * 8;
                        float gi = half ? acc[mt][nt][2] : acc[mt][nt][0];
                        float gj = half ? acc[mt][nt][3] : acc[mt][nt][1];
                        float gf = half ? fo2 : fo0;
                        float go = half ? fo3 : fo1;
                        int c0 = n0 + wid * 32 + nt * 8 + (lane & 3) * 2;
                        int j = c0 >> 2;
                        float4 x = *(const float4*)(Xg + ((size_t)bb * T_ + t) * G4_ + c0);
                        gi += x.x; gj += x.y; gf += x.z; go += x.w;
                        size_t ci = (size_t)bb * H_ + j;
                        float yv = 0.f;
                        if (t < sl[bb]) {
                            float cc = cst[ci];
                            float cn = cc * sigf(gf + 1.f) + sigf(gi) * ftanh(gj);
                            float hn = ftanh(cn) * sigf(go);
                            cst[ci] = cn;
                            hout[ci] = hn;
                            yv = hn;
                        } else {
                            hout[ci] = __ldcg(hin + ci);
                        }
                        Yst[((size_t)bb * T_ + t) * H_ + j] = yv;
                    }
                }
            }
        }
        gbar(sync + 0, sync + 1, (unsigned)(t + 1), 128u);
    }
}

// ---------------- persistent attention scan ----------------
__global__ void __launch_bounds__(128) k_att_persist(
    const float* __restrict__ wv,
    const int* __restrict__ s1, const int* __restrict__ s2) {
    extern __shared__ __align__(16) char smem_raw[];
    uint32_t sb = smem_u32(smem_raw);
    float* smf = (float*)smem_raw;
    float* buf = d_buf;
    int tid = threadIdx.x, lane = tid & 31, wid = tid >> 5;
    int blk = blockIdx.x;

    int ks  = blk & 3;
    int mt_ = (blk >> 2) & 3;
    int nt_ = blk >> 4;
    int m0 = mt_ * TM, n0 = nt_ * TN, kst = ks * 128;

    const __nv_bfloat16* WcS = (const __nv_bfloat16*)(buf + OFF_WCS);
    const __nv_bfloat16* Bhg = WcS + (size_t)(n0 + tid) * H_ + kst;
    const __nv_bfloat16* Blg = WcS + 2ull * H_ * H_ + (size_t)(n0 + tid) * H_ + kst;

    float* rbuf = buf + OFF_R;
    float* uPt4 = buf + OFF_UPT;
    float* rL   = buf + OFF_RL;
    const float* WyY = buf + OFF_WYY;
    const float* HWy = buf + OFF_HWY;
    const float* Yb  = buf + OFF_Y;
    unsigned* sync = (unsigned*)(buf + OFF_SYNC);

    uint32_t aSt = (uint32_t)((tid >> 1) * PAD + (tid & 1) * 16) * 2;
    uint32_t bSt = (uint32_t)(tid * PAD) * 2;
    uint32_t aLd = (uint32_t)((lane & 15) * PAD + ((lane >> 4) << 3)) * 2;
    uint32_t bLd = (uint32_t)(((lane & 7) + ((lane & 16) >> 1)) * PAD + (lane & 8)) * 2;

    // wv preloaded once into registers (constant across steps/pairs)
    float wvr[16];
#pragma unroll
    for (int k = 0; k < 16; k++) wvr[k] = __ldg(wv + lane + 32 * k);

    // per-CTA pair info (uniform across threads)
    int pA = blk * 2, pB = blk * 2 + 1;
    int aA = pA >> 7, bA = pA & 127;
    int aB = pB >> 7, bB = pB & 127;
    int sl2A = aA ? s1[bA] : s2[bA];
    int sl2B = aB ? s1[bB] : s2[bB];
    int slmA = aA ? s2[bA] : s1[bA];
    int slmB = aB ? s2[bB] : s1[bB];

    for (int t = 0; t < T_; t++) {
        // ---- phase G: uPt4[ks] = rbuf(kslice) @ Wc ----
        {
            const float* Ag = rbuf + (size_t)(m0 + (tid >> 1)) * H_ + kst + (tid & 1) * 16;
            float acc[4][4][4] = {};
            gemm_k(Ag, Bhg, Blg, 4, smem_raw, sb, aSt, bSt, aLd, bLd, wid, acc);
            float* Cb = uPt4 + (size_t)ks * 256 * 1024;
#pragma unroll
            for (int mt = 0; mt < 4; mt++) {
                int r = m0 + mt * 16 + (lane >> 2);
#pragma unroll
                for (int nt = 0; nt < 4; nt++) {
                    int c = n0 + wid * 32 + nt * 8 + (lane & 3) * 2;
                    *(float2*)(Cb + (size_t)r * 1024 + c) =
                        make_float2(acc[mt][nt][0], acc[mt][nt][1]);
                    *(float2*)(Cb + (size_t)(r + 8) * 1024 + c) =
                        make_float2(acc[mt][nt][2], acc[mt][nt][3]);
                }
            }
        }
        gbar(sync + 2, sync + 3, (unsigned)(2 * t + 1), 128u);

        // ---- phase A: two (a,b) pairs, with exact step/mask skipping ----
        for (int pi = 0; pi < 2; pi++) {
            int p    = pi ? pB : pA;
            int a    = pi ? aB : aA;
            int b    = pi ? bB : bA;
            int sl2  = pi ? sl2B : sl2A;
            int slm  = pi ? slmB : slmA;
            if (t >= sl2) continue;   // r never consumed past sl2-1 (uniform branch)

            float* su  = smf;
            float* spt = smf + 512;
            float* sc  = smf + 1024;
            const float* hb = HWy + (size_t)a * B_ * T_ * H_ + ((size_t)b * T_ + t) * H_;
#pragma unroll
            for (int q = 0; q < 4; q++) {
                int h = tid + q * 128;
                float s0 = 0.f, s1v = 0.f;
#pragma unroll
                for (int k = 0; k < 4; k++) {
                    const float* up = uPt4 + ((size_t)k * 256 + p) * 1024;
                    s0  += __ldcg(up + h);
                    s1v += __ldcg(up + 512 + h);
                }
                su[h]  = s0 + __ldg(hb + h);
                spt[h] = s1v;
            }
            __syncthreads();
            // scores: compute only t2 < slm (masked entries exact -1e4 -> alpha 0)
            const float* WyYb = WyY + (size_t)a * B_ * T_ * H_ + (size_t)b * T_ * H_;
#pragma unroll
            for (int q = 0; q < 16; q++) {
                int t2 = wid * 16 + q;
                if (t2 < slm) {
                    const float* row = WyYb + (size_t)t2 * H_;
                    float s = 0.f;
#pragma unroll
                    for (int k = 0; k < 16; k++) {
                        int hh = lane + 32 * k;
                        s += tanha(__ldg(row + hh) + su[hh]) * wvr[k];
                    }
                    for (int o = 16; o; o >>= 1) s += __shfl_xor_sync(0xffffffffu, s, o);
                    if (lane == 0) sc[t2] = s;
                } else if (lane == 0) {
                    sc[t2] = -10000.f;
                }
            }
            __syncthreads();
            if (wid == 0) {
                float v1 = sc[lane], v2 = sc[lane + 32];
                float m = fmaxf(v1, v2);
                for (int o = 16; o; o >>= 1) m = fmaxf(m, __shfl_xor_sync(0xffffffffu, m, o));
                float e1 = __expf(v1 - m), e2 = __expf(v2 - m);
                float s = e1 + e2;
                for (int o = 16; o; o >>= 1) s += __shfl_xor_sync(0xffffffffu, s, o);
                float inv = __fdividef(1.f, s);
                sc[lane] = e1 * inv;
                sc[lane + 32] = e2 * inv;
            }
            __syncthreads();
            // context over t2 < slm only (alpha is exactly 0 beyond)
            const float* Yp = Yb + (size_t)(a ? 2 : 0) * B_ * T_ * H_ + (size_t)b * T_ * H_;
#pragma unroll
            for (int q = 0; q < 4; q++) {
                int h = tid + q * 128;
                float accv = 0.f;
                for (int t2 = 0; t2 < slm; t2++)
                    accv += sc[t2] * __ldg(Yp + (size_t)t2 * H_ + h);
                float rn = accv + ftanh(spt[h]);
                if (t == sl2 - 1) rL[(size_t)p * H_ + h] = rn;
                else              rbuf[(size_t)p * H_ + h] = rn;
            }
            __syncthreads();
        }
        gbar(sync + 2, sync + 3, (unsigned)(2 * t + 2), 128u);
    }
}

// ---------------- final projection ----------------
__global__ void __launch_bounds__(512) k_final(
    const float* __restrict__ rL, const float* __restrict__ hfin,
    const float* __restrict__ Wp, const float* __restrict__ Wx,
    const float* __restrict__ U, const float* __restrict__ bU,
    float* __restrict__ out) {
    int b = blockIdx.x;
    int tid = threadIdx.x;
    __shared__ float s_in[4][512];
    __shared__ float s_sum[512];
    __shared__ float red0[16], red1[16];
    s_in[0][tid] = rL[(size_t)b * H_ + tid];
    s_in[1][tid] = hfin[((size_t)1 * B_ + b) * H_ + tid];
    s_in[2][tid] = rL[((size_t)B_ + b) * H_ + tid];
    s_in[3][tid] = hfin[((size_t)3 * B_ + b) * H_ + tid];
    __syncthreads();
    float acc0 = 0.f, acc1 = 0.f;
    for (int k = 0; k < H_; k++) {
        float wp = Wp[(size_t)k * H_ + tid];
        float wx = Wx[(size_t)k * H_ + tid];
        acc0 += s_in[0][k] * wp + s_in[1][k] * wx;
        acc1 += s_in[2][k] * wp + s_in[3][k] * wx;
    }
    s_sum[tid] = ftanh(acc0) + ftanh(acc1);
    __syncthreads();
    float p0 = s_sum[tid] * U[(size_t)tid * 2 + 0];
    float p1 = s_sum[tid] * U[(size_t)tid * 2 + 1];
    for (int o = 16; o; o >>= 1) {
        p0 += __shfl_xor_sync(0xffffffffu, p0, o);
        p1 += __shfl_xor_sync(0xffffffffu, p1, o);
    }
    int wp_ = tid >> 5;
    if ((tid & 31) == 0) { red0[wp_] = p0; red1[wp_] = p1; }
    __syncthreads();
    if (tid < 16) {
        p0 = red0[tid]; p1 = red1[tid];
        for (int o = 8; o; o >>= 1) {
            p0 += __shfl_xor_sync(0x0000ffffu, p0, o);
            p1 += __shfl_xor_sync(0x0000ffffu, p1, o);
        }
        if (tid == 0) {
            out[b * 2 + 0] = p0 + bU[0];
            out[b * 2 + 1] = p1 + bU[1];
        }
    }
}

// ---------------- host ----------------
extern "C" void kernel_launch(void* const* d_in, const int* in_sizes, int n_in,
                              void* d_out, int out_size) {
    (void)in_sizes; (void)n_in; (void)out_size;
    const int*   tokens1 = (const int*)d_in[0];
    const int*   tokens2 = (const int*)d_in[1];
    const int*   seqlen1 = (const int*)d_in[2];
    const int*   seqlen2 = (const int*)d_in[3];
    const float* emb = (const float*)d_in[4];
    const float* W1  = (const float*)d_in[5];
    const float* b1  = (const float*)d_in[6];
    const float* W2  = (const float*)d_in[7];
    const float* b2  = (const float*)d_in[8];
    const float* Wy  = (const float*)d_in[9];
    const float* Wh  = (const float*)d_in[10];
    const float* Wr  = (const float*)d_in[11];
    const float* wv  = (const float*)d_in[12];
    const float* Wt  = (const float*)d_in[13];
    const float* Wp  = (const float*)d_in[14];
    const float* Wx  = (const float*)d_in[15];
    const float* U   = (const float*)d_in[16];
    const float* bU  = (const float*)d_in[17];
    float* out = (float*)d_out;

    cudaFuncSetAttribute(mm_gemm, cudaFuncAttributeMaxDynamicSharedMemorySize, SMEM_MM);
    cudaFuncSetAttribute(k_lstm_persist, cudaFuncAttributeMaxDynamicSharedMemorySize, SMEM_MM);
    cudaFuncSetAttribute(k_att_persist, cudaFuncAttributeMaxDynamicSharedMemorySize, SMEM_MM);

    float* buf = nullptr;
    cudaGetSymbolAddress((void**)&buf, d_buf);
    float* e    = buf + OFF_E;
    float* Xg   = buf + OFF_XG;
    float* Yb   = buf + OFF_Y;
    float* hBuf = buf + OFF_H;
    float* WyY  = buf + OFF_WYY;
    float* HWy  = buf + OFF_HWY;
    float* rL   = buf + OFF_RL;
    float* bP   = buf + OFF_BP;
    __nv_bfloat16* WxS = (__nv_bfloat16*)(buf + OFF_WXS);
    __nv_bfloat16* WyS = (__nv_bfloat16*)(buf + OFF_WYS);
    __nv_bfloat16* WhA = (__nv_bfloat16*)(buf + OFF_WHA);

    // launch #1, #2 (zero-init folded into k_prep)
    k_prep<<<1024, 256>>>(W1, W2, Wy, Wh, Wr, Wt, b1, b2);
    k_gather<<<2048, 256>>>(e, tokens1, tokens2, emb);

    const int iidx[4] = {0, 1, 1, 0}, widx[4] = {0, 1, 0, 1};

    // launch #3: X-part GEMM
    {
        MP p = {};
        for (int r = 0; r < 4; r++) {
            p.z[r].A    = e + (size_t)iidx[r] * B_ * T_ * KPX;
            p.z[r].Bhi  = WxS + (size_t)(widx[r] * 2 + 0) * G4_ * KPX;
            p.z[r].Blo  = WxS + (size_t)(widx[r] * 2 + 1) * G4_ * KPX;
            p.z[r].C    = Xg + (size_t)r * B_ * T_ * G4_;
            p.z[r].bias = bP + (size_t)widx[r] * G4_;
        }
        p.Klen = KPX; p.lda = KPX; p.ldb = KPX; p.ldc = G4_;
        mm_gemm<<<dim3(G4_ / TN, (B_ * T_) / TM, 4), 128, SMEM_MM>>>(p);
    }

    // launch #4 (ncu capture target): persistent LSTM scan
    k_lstm_persist<<<128, 128, SMEM_MM>>>(seqlen1, seqlen2);

    // launch #5: WyY + HWy
    {
        MP p = {};
        const int runs[4] = {0, 2, 1, 3};
        for (int q = 0; q < 4; q++) {
            p.z[q].A   = Yb + (size_t)runs[q] * B_ * T_ * H_;
            p.z[q].Bhi = (q < 2 ? WyS : WhA);
            p.z[q].Blo = (q < 2 ? WyS : WhA) + (size_t)H_ * H_;
            p.z[q].C   = (q < 2 ? WyY + (size_t)q * B_ * T_ * H_
                                : HWy + (size_t)(q - 2) * B_ * T_ * H_);
            p.z[q].bias = nullptr;
        }
        p.Klen = H_; p.lda = H_; p.ldb = H_; p.ldc = H_;
        mm_gemm<<<dim3(H_ / TN, (B_ * T_) / TM, 4), 128, SMEM_MM>>>(p);
    }

    // launch #6: persistent attention scan
    k_att_persist<<<128, 128, SMEM_MM>>>(wv, seqlen1, seqlen2);

    // launch #7
    k_final<<<B_, 512>>>(rL, hBuf, Wp, Wx, U, bU, out);
}